// round 13
// baseline (speedup 1.0000x reference)
#include <cuda_runtime.h>
#include <cuda_fp16.h>
#include <math.h>
#include <stdint.h>

#define B_   4
#define S_   2048
#define HID_ 1024
#define NH_  4
#define D_   256
#define IM_  2048
#define E_   4
#define T_   (B_*S_)   // 8192 tokens

// ---------------- scratch ----------------
__device__ float g_scores[(size_t)B_*NH_*S_*S_];            // 256 MB (f32 scores)
__device__ float g_h1[(size_t)T_*HID_];
__device__ float g_x2[(size_t)T_*HID_];
__device__ float g_rw[(size_t)T_*E_];
__device__ float g_red[S_];
__device__ float g_dpart[(size_t)E_*T_*HID_];               // 128 MB per-expert down partials
// half operands
__device__ __align__(16) __half g_probs[(size_t)B_*NH_*S_*S_];  // 128 MB
__device__ __align__(16) __half g_xnh[(size_t)T_*HID_];
__device__ __align__(16) __half g_xnl[(size_t)T_*HID_];
__device__ __align__(16) __half g_x2h[(size_t)T_*HID_];
__device__ __align__(16) __half g_qkh[(size_t)2*T_*HID_];   // q | k (hi)
__device__ __align__(16) __half g_qkl[(size_t)2*T_*HID_];   // q | k (lo)
__device__ __align__(16) __half g_vh[(size_t)T_*HID_];
__device__ __align__(16) __half g_vth[(size_t)B_*NH_*D_*S_];
__device__ __align__(16) __half g_oh[(size_t)T_*HID_];
__device__ __align__(16) __half g_gbh[(size_t)E_*T_*IM_];   // 128 MB
__device__ __align__(16) __half g_ubh[(size_t)E_*T_*IM_];   // 128 MB
// transposed half weights [N,K]
__device__ __align__(16) __half g_wqkTh[(size_t)2*HID_*HID_];  // wq | wk (hi)
__device__ __align__(16) __half g_wqkTl[(size_t)2*HID_*HID_];  // wq | wk (lo)
__device__ __align__(16) __half g_wvT[(size_t)HID_*HID_];
__device__ __align__(16) __half g_woT[(size_t)HID_*HID_];
__device__ __align__(16) __half g_gT[(size_t)E_*IM_*HID_];
__device__ __align__(16) __half g_uT[(size_t)E_*IM_*HID_];
__device__ __align__(16) __half g_dT[(size_t)E_*HID_*IM_];

// ---------------- helpers ----------------
__device__ __forceinline__ void cp16(void* dst, const void* src) {
    uint32_t d = (uint32_t)__cvta_generic_to_shared(dst);
    asm volatile("cp.async.cg.shared.global [%0], [%1], 16;" :: "r"(d), "l"(src));
}
#define CP_COMMIT() asm volatile("cp.async.commit_group;" ::: "memory")
template<int N> __device__ __forceinline__ void cp_wait() {
    asm volatile("cp.async.wait_group %0;" :: "n"(N) : "memory");
}
__device__ __forceinline__ void mma_f16(float* c, const unsigned* a, const unsigned* b) {
    asm volatile("mma.sync.aligned.m16n8k16.row.col.f32.f16.f16.f32 "
                 "{%0,%1,%2,%3},{%4,%5,%6,%7},{%8,%9},{%0,%1,%2,%3};"
                 : "+f"(c[0]), "+f"(c[1]), "+f"(c[2]), "+f"(c[3])
                 : "r"(a[0]), "r"(a[1]), "r"(a[2]), "r"(a[3]),
                   "r"(b[0]), "r"(b[1]));
}

__device__ __forceinline__ float blk_sum(float v) {
    __shared__ float sm[32];
    __syncthreads();
    int lane = threadIdx.x & 31, w = threadIdx.x >> 5;
    #pragma unroll
    for (int o = 16; o; o >>= 1) v += __shfl_down_sync(0xffffffffu, v, o);
    if (lane == 0) sm[w] = v;
    __syncthreads();
    int nw = blockDim.x >> 5;
    if (w == 0) {
        v = (lane < nw) ? sm[lane] : 0.f;
        #pragma unroll
        for (int o = 16; o; o >>= 1) v += __shfl_down_sync(0xffffffffu, v, o);
        if (lane == 0) sm[0] = v;
    }
    __syncthreads();
    return sm[0];
}
__device__ __forceinline__ float blk_max(float v) {
    __shared__ float sm[32];
    __syncthreads();
    int lane = threadIdx.x & 31, w = threadIdx.x >> 5;
    #pragma unroll
    for (int o = 16; o; o >>= 1) v = fmaxf(v, __shfl_down_sync(0xffffffffu, v, o));
    if (lane == 0) sm[w] = v;
    __syncthreads();
    int nw = blockDim.x >> 5;
    if (w == 0) {
        v = (lane < nw) ? sm[lane] : -INFINITY;
        #pragma unroll
        for (int o = 16; o; o >>= 1) v = fmaxf(v, __shfl_down_sync(0xffffffffu, v, o));
        if (lane == 0) sm[0] = v;
    }
    __syncthreads();
    return sm[0];
}

// ---------------- rmsnorm (f32 out optional; half hi/lo optional) ----------------
__global__ void rmsnorm_kernel(const float* __restrict__ x, const float* __restrict__ w,
                               float* __restrict__ outf,
                               __half* __restrict__ outh, __half* __restrict__ outl) {
    size_t t = blockIdx.x;
    float4 v = ((const float4*)(x + t * HID_))[threadIdx.x];
    float s = v.x*v.x + v.y*v.y + v.z*v.z + v.w*v.w;
    s = blk_sum(s);
    float r = rsqrtf(s * (1.f / HID_) + 1e-6f);
    float4 wv = ((const float4*)w)[threadIdx.x];
    float4 o;
    o.x = v.x * wv.x * r; o.y = v.y * wv.y * r;
    o.z = v.z * wv.z * r; o.w = v.w * wv.w * r;
    if (outf) ((float4*)(outf + t * HID_))[threadIdx.x] = o;
    if (outh) {
        __half2 h01 = __floats2half2_rn(o.x, o.y);
        __half2 h23 = __floats2half2_rn(o.z, o.w);
        ((__half2*)(outh + t * HID_))[2 * threadIdx.x + 0] = h01;
        ((__half2*)(outh + t * HID_))[2 * threadIdx.x + 1] = h23;
        if (outl) {
            __half2 l01 = __floats2half2_rn(o.x - __low2float(h01), o.y - __high2float(h01));
            __half2 l23 = __floats2half2_rn(o.z - __low2float(h23), o.w - __high2float(h23));
            ((__half2*)(outl + t * HID_))[2 * threadIdx.x + 0] = l01;
            ((__half2*)(outl + t * HID_))[2 * threadIdx.x + 1] = l23;
        }
    }
}

// ---------------- weight transpose f32[R,C] -> half[C,R] (hi, opt lo); batched z ----------------
template<bool SPL>
__global__ void trw_kernel(__half* __restrict__ oh, __half* __restrict__ ol,
                           const float* __restrict__ in, int R, int C) {
    __shared__ float tile[32][33];
    long zo = (long)blockIdx.z * R * C;
    in += zo; oh += zo; if (SPL) ol += zo;
    int c0 = blockIdx.x * 32, r0 = blockIdx.y * 32;
    int x = threadIdx.x, y = threadIdx.y;
    #pragma unroll
    for (int i = 0; i < 32; i += 8)
        tile[y + i][x] = in[(long)(r0 + y + i) * C + c0 + x];
    __syncthreads();
    #pragma unroll
    for (int i = 0; i < 32; i += 8) {
        float f = tile[x][y + i];
        __half h = __float2half_rn(f);
        long idx = (long)(c0 + y + i) * R + r0 + x;
        oh[idx] = h;
        if (SPL) ol[idx] = __float2half_rn(f - __half2float(h));
    }
}

// ---------------- v transpose: half vh[T,HID] per-(b,h) [S,D] -> vth[bh][D,S] ----------------
__global__ void trv_kernel(__half* __restrict__ out, const __half* __restrict__ in) {
    __shared__ __half tile[32][33];
    int z = blockIdx.z, zb = z >> 2, zh = z & 3;
    const __half* ip = in + (long)zb * S_ * HID_ + (long)zh * D_;
    __half* op = out + (long)z * D_ * S_;
    int c0 = blockIdx.x * 32, r0 = blockIdx.y * 32;
    int x = threadIdx.x, y = threadIdx.y;
    #pragma unroll
    for (int i = 0; i < 32; i += 8)
        tile[y + i][x] = ip[(long)(r0 + y + i) * HID_ + c0 + x];
    __syncthreads();
    #pragma unroll
    for (int i = 0; i < 32; i += 8)
        op[(long)(c0 + y + i) * S_ + r0 + x] = tile[x][y + i];
}

// ================= half NT GEMM with cp.async (m16n8k16), 128x128 tile =================
// C = A[M,K] * B[N,K]^T. SPLIT: A,B given as (hi,lo) pairs.
// Non-split: TBK=64, 3 stages; split: TBK=32, 2 stages. Both occupancy 2.
// EPI: 0 f32 store | 1 elu+1 -> half hi(C)+lo(aux) | 2 f32 C=v+auxf | 3 silu->half
//      4 v*auxh->half | 7 half store | 8 f32 C = v * rs[m*rsStride + zh]

template<int EPI, bool SPLIT>
__global__ __launch_bounds__(256, 2)
void hgemm(int M, int N, int K,
           const __half* __restrict__ Ahg, const __half* __restrict__ Alg, int lda, long sAb, long sAh,
           const __half* __restrict__ Bhg, const __half* __restrict__ Blg, int ldb, long sBb, long sBh,
           void* __restrict__ Cv, int ldc, long sCb, long sCh,
           void* __restrict__ aux,
           const float* __restrict__ rs, int rsStride) {
    constexpr int TBK   = SPLIT ? 32 : 64;
    constexpr int PITCH = TBK + 8;                  // 40 or 72 halves
    constexpr int SZT   = 128 * PITCH * 2;          // bytes per tile
    constexpr int NTIL  = SPLIT ? 4 : 2;
    constexpr int STAGE = NTIL * SZT;
    constexpr int NSTG  = SPLIT ? 2 : 3;
    constexpr int SEGS  = TBK / 8;                  // 16B segs per row

    int z  = blockIdx.z;
    int zb = z >> 2, zh = z & 3;
    Ahg += (long)zb * sAb + (long)zh * sAh;
    Bhg += (long)zb * sBb + (long)zh * sBh;
    if (SPLIT) { Alg += (long)zb * sAb + (long)zh * sAh; Blg += (long)zb * sBb + (long)zh * sBh; }
    long coff = (long)zb * sCb + (long)zh * sCh;

    extern __shared__ char smem[];

    int tid  = threadIdx.x;
    int lane = tid & 31;
    int warp = tid >> 5;
    int wm = (warp >> 2) * 64;
    int wn = (warp & 3) * 32;
    int g = lane >> 2;
    int t = lane & 3;

    int blockRow = blockIdx.y * 128;
    int blockCol = blockIdx.x * 128;
    const __half* Ab = Ahg + (long)blockRow * lda;
    const __half* Bb = Bhg + (long)blockCol * ldb;
    const __half* Alb = SPLIT ? Alg + (long)blockRow * lda : nullptr;
    const __half* Blb = SPLIT ? Blg + (long)blockCol * ldb : nullptr;

    int nIter = K / TBK;

    auto issue = [&](int st, int kt) {
        if (kt < nIter) {
            long k0 = (long)kt * TBK;
            char* sb = smem + st * STAGE;
            __half* As = (__half*)sb;
            __half* Bs = (__half*)(sb + SZT);
            #pragma unroll
            for (int c = 0; c < SEGS / 2; c++) {
                int idx = tid + c * 256;
                int row = idx / SEGS;
                int seg = (idx % SEGS) * 8;
                cp16(&As[row * PITCH + seg], Ab + (long)row * lda + k0 + seg);
                cp16(&Bs[row * PITCH + seg], Bb + (long)row * ldb + k0 + seg);
                if (SPLIT) {
                    __half* Als = (__half*)(sb + 2 * SZT);
                    __half* Bls = (__half*)(sb + 3 * SZT);
                    cp16(&Als[row * PITCH + seg], Alb + (long)row * lda + k0 + seg);
                    cp16(&Bls[row * PITCH + seg], Blb + (long)row * ldb + k0 + seg);
                }
            }
        }
        CP_COMMIT();
    };

    float acc[4][4][4] = {};

    issue(0, 0);
    issue(1 % NSTG, 1);
    for (int kt = 0; kt < nIter; kt++) {
        int st = kt % NSTG;
        cp_wait<1>();
        __syncthreads();
        char* sb = smem + st * STAGE;
        const __half* As = (const __half*)sb;
        const __half* Bs = (const __half*)(sb + SZT);
        const __half* Als = (const __half*)(sb + 2 * SZT);
        const __half* Bls = (const __half*)(sb + 3 * SZT);

        #pragma unroll
        for (int ks = 0; ks < TBK; ks += 16) {
            unsigned a[4][4], b[4][2];
            #pragma unroll
            for (int mi = 0; mi < 4; mi++) {
                const __half* base = As + (wm + mi * 16 + g) * PITCH + ks + 2 * t;
                a[mi][0] = *(const unsigned*)(base);
                a[mi][1] = *(const unsigned*)(base + 8 * PITCH);
                a[mi][2] = *(const unsigned*)(base + 8);
                a[mi][3] = *(const unsigned*)(base + 8 * PITCH + 8);
            }
            #pragma unroll
            for (int ni = 0; ni < 4; ni++) {
                const __half* base = Bs + (wn + ni * 8 + g) * PITCH + ks + 2 * t;
                b[ni][0] = *(const unsigned*)(base);
                b[ni][1] = *(const unsigned*)(base + 8);
            }
            if (!SPLIT) {
                #pragma unroll
                for (int mi = 0; mi < 4; mi++)
                    #pragma unroll
                    for (int ni = 0; ni < 4; ni++)
                        mma_f16(acc[mi][ni], a[mi], b[ni]);
            } else {
                unsigned al[4][4], bl[4][2];
                #pragma unroll
                for (int mi = 0; mi < 4; mi++) {
                    const __half* base = Als + (wm + mi * 16 + g) * PITCH + ks + 2 * t;
                    al[mi][0] = *(const unsigned*)(base);
                    al[mi][1] = *(const unsigned*)(base + 8 * PITCH);
                    al[mi][2] = *(const unsigned*)(base + 8);
                    al[mi][3] = *(const unsigned*)(base + 8 * PITCH + 8);
                }
                #pragma unroll
                for (int ni = 0; ni < 4; ni++) {
                    const __half* base = Bls + (wn + ni * 8 + g) * PITCH + ks + 2 * t;
                    bl[ni][0] = *(const unsigned*)(base);
                    bl[ni][1] = *(const unsigned*)(base + 8);
                }
                #pragma unroll
                for (int mi = 0; mi < 4; mi++)
                    #pragma unroll
                    for (int ni = 0; ni < 4; ni++) {
                        mma_f16(acc[mi][ni], a[mi], bl[ni]);
                        mma_f16(acc[mi][ni], al[mi], b[ni]);
                        mma_f16(acc[mi][ni], a[mi], b[ni]);
                    }
            }
        }
        __syncthreads();
        issue((kt + 2) % NSTG, kt + 2);
    }

    // ---- epilogue ----
    float* Cf = (float*)Cv + coff;
    __half* Ch = (__half*)Cv + coff;
    const float* auxf = (const float*)aux ? (const float*)aux + coff : nullptr;
    const __half* auxh = (const __half*)aux ? (const __half*)aux + coff : nullptr;
    __half* aux2h = (__half*)aux ? (__half*)aux + coff : nullptr;

    #pragma unroll
    for (int mi = 0; mi < 4; mi++) {
        int r0 = blockRow + wm + mi * 16 + g;
        int r1 = r0 + 8;
        float sc0 = 0.f, sc1 = 0.f;
        if (EPI == 8) {
            sc0 = rs[(long)r0 * rsStride + zh];
            sc1 = rs[(long)r1 * rsStride + zh];
        }
        #pragma unroll
        for (int ni = 0; ni < 4; ni++) {
            int col = blockCol + wn + ni * 8 + 2 * t;
            long i0 = (long)r0 * ldc + col;
            long i1 = (long)r1 * ldc + col;
            float v0 = acc[mi][ni][0], v1 = acc[mi][ni][1];
            float v2 = acc[mi][ni][2], v3 = acc[mi][ni][3];
            if (EPI == 0) {
                *(float2*)(Cf + i0) = make_float2(v0, v1);
                *(float2*)(Cf + i1) = make_float2(v2, v3);
            } else if (EPI == 1) {
                float e0 = (v0 > 0.f) ? v0 + 1.f : expf(v0);
                float e1 = (v1 > 0.f) ? v1 + 1.f : expf(v1);
                float e2 = (v2 > 0.f) ? v2 + 1.f : expf(v2);
                float e3 = (v3 > 0.f) ? v3 + 1.f : expf(v3);
                __half2 h0 = __floats2half2_rn(e0, e1);
                __half2 h1v = __floats2half2_rn(e2, e3);
                *(__half2*)(Ch + i0) = h0;
                *(__half2*)(Ch + i1) = h1v;
                *(__half2*)(aux2h + i0) = __floats2half2_rn(e0 - __low2float(h0), e1 - __high2float(h0));
                *(__half2*)(aux2h + i1) = __floats2half2_rn(e2 - __low2float(h1v), e3 - __high2float(h1v));
            } else if (EPI == 2) {
                float2 x0 = *(const float2*)(auxf + i0);
                float2 x1 = *(const float2*)(auxf + i1);
                *(float2*)(Cf + i0) = make_float2(v0 + x0.x, v1 + x0.y);
                *(float2*)(Cf + i1) = make_float2(v2 + x1.x, v3 + x1.y);
            } else if (EPI == 3) {
                *(__half2*)(Ch + i0) = __floats2half2_rn(v0 / (1.f + expf(-v0)), v1 / (1.f + expf(-v1)));
                *(__half2*)(Ch + i1) = __floats2half2_rn(v2 / (1.f + expf(-v2)), v3 / (1.f + expf(-v3)));
            } else if (EPI == 4) {
                __half2 g0 = *(const __half2*)(auxh + i0);
                __half2 g1 = *(const __half2*)(auxh + i1);
                *(__half2*)(Ch + i0) = __floats2half2_rn(v0 * __low2float(g0), v1 * __high2float(g0));
                *(__half2*)(Ch + i1) = __floats2half2_rn(v2 * __low2float(g1), v3 * __high2float(g1));
            } else if (EPI == 8) {
                *(float2*)(Cf + i0) = make_float2(v0 * sc0, v1 * sc0);
                *(float2*)(Cf + i1) = make_float2(v2 * sc1, v3 * sc1);
            } else { // 7
                *(__half2*)(Ch + i0) = __floats2half2_rn(v0, v1);
                *(__half2*)(Ch + i1) = __floats2half2_rn(v2, v3);
            }
        }
    }
}

#define SMEM_NS (3 * 2 * (128 * 72 * 2))   // 110592, occ 2
#define SMEM_SP (2 * 4 * (128 * 40 * 2))   // 81920, occ 2

// ---------------- MoE reduce: out = h1 + sum_e dpart[e] ----------------
__global__ void moe_reduce_kernel(float* __restrict__ out, const float* __restrict__ h1,
                                  const float* __restrict__ dp) {
    size_t i = (size_t)blockIdx.x * 256 + threadIdx.x;
    const size_t n = (size_t)T_ * HID_;
    float4 r = ((const float4*)h1)[i];
    #pragma unroll
    for (int e = 0; e < E_; e++) {
        float4 p = ((const float4*)(dp + e * n))[i];
        r.x += p.x; r.y += p.y; r.z += p.z; r.w += p.w;
    }
    ((float4*)out)[i] = r;
}

// ---------------- softmax: f32 scores -> half probs ----------------
__global__ void softmax_kernel(const float* __restrict__ x, __half* __restrict__ pr) {
    size_t row = blockIdx.x;
    const float4* p = (const float4*)(x + row * (size_t)S_);
    float4 a = p[threadIdx.x];
    float4 b = p[threadIdx.x + 256];
    float mx = fmaxf(fmaxf(fmaxf(a.x, a.y), fmaxf(a.z, a.w)),
                     fmaxf(fmaxf(b.x, b.y), fmaxf(b.z, b.w)));
    mx = blk_max(mx);
    a.x = expf(a.x - mx); a.y = expf(a.y - mx); a.z = expf(a.z - mx); a.w = expf(a.w - mx);
    b.x = expf(b.x - mx); b.y = expf(b.y - mx); b.z = expf(b.z - mx); b.w = expf(b.w - mx);
    float s = a.x + a.y + a.z + a.w + b.x + b.y + b.z + b.w;
    s = blk_sum(s);
    float inv = 1.f / s;
    __half2* o = (__half2*)(pr + row * (size_t)S_);
    o[2 * threadIdx.x + 0]   = __floats2half2_rn(a.x * inv, a.y * inv);
    o[2 * threadIdx.x + 1]   = __floats2half2_rn(a.z * inv, a.w * inv);
    o[2 * (threadIdx.x + 256) + 0] = __floats2half2_rn(b.x * inv, b.y * inv);
    o[2 * (threadIdx.x + 256) + 1] = __floats2half2_rn(b.z * inv, b.w * inv);
}

// ---------------- router ----------------
__global__ void router_kernel(const float* __restrict__ x2,
                              const float* __restrict__ rwW,
                              const float* __restrict__ rb,
                              float* __restrict__ rwOut) {
    size_t t = blockIdx.x;
    const float* x = x2 + t * HID_;
    float s0 = 0, s1 = 0, s2 = 0, s3 = 0;
    for (int j = threadIdx.x; j < HID_; j += 256) {
        float xv = x[j];
        float4 w = ((const float4*)rwW)[j];
        s0 = fmaf(xv, w.x, s0); s1 = fmaf(xv, w.y, s1);
        s2 = fmaf(xv, w.z, s2); s3 = fmaf(xv, w.w, s3);
    }
    __shared__ float sm[8][4];
    int lane = threadIdx.x & 31, w = threadIdx.x >> 5;
    #pragma unroll
    for (int o = 16; o; o >>= 1) {
        s0 += __shfl_down_sync(0xffffffffu, s0, o);
        s1 += __shfl_down_sync(0xffffffffu, s1, o);
        s2 += __shfl_down_sync(0xffffffffu, s2, o);
        s3 += __shfl_down_sync(0xffffffffu, s3, o);
    }
    if (lane == 0) { sm[w][0] = s0; sm[w][1] = s1; sm[w][2] = s2; sm[w][3] = s3; }
    __syncthreads();
    if (threadIdx.x == 0) {
        float l[4];
        #pragma unroll
        for (int e = 0; e < 4; e++) {
            float v = 0;
            #pragma unroll
            for (int ww = 0; ww < 8; ww++) v += sm[ww][e];
            l[e] = v + rb[e];
        }
        float mx = fmaxf(fmaxf(l[0], l[1]), fmaxf(l[2], l[3]));
        float sum = 0;
        #pragma unroll
        for (int e = 0; e < 4; e++) { l[e] = expf(l[e] - mx); sum += l[e]; }
        float inv = 1.f / sum;
        #pragma unroll
        for (int e = 0; e < 4; e++) rwOut[t * E_ + e] = l[e] * inv;
    }
}

// ---------------- balance loss ----------------
__global__ void balance1_kernel(const float* __restrict__ rw, float* __restrict__ red) {
    int s = blockIdx.x;
    if (threadIdx.x < 4) {
        int e = threadIdx.x;
        float m = 0;
        #pragma unroll
        for (int b = 0; b < B_; b++) m += rw[((size_t)(b * S_ + s)) * E_ + e];
        m = m * (1.f / B_) - (1.f / E_);
        float v = m * m;
        v += __shfl_xor_sync(0xF, v, 1);
        v += __shfl_xor_sync(0xF, v, 2);
        if (e == 0) red[s] = v;
    }
}
__global__ void balance2_kernel(const float* __restrict__ red, float* __restrict__ out) {
    float v = red[threadIdx.x] + red[threadIdx.x + 1024];
    v = blk_sum(v);
    if (threadIdx.x == 0) out[0] = v / ((float)S_ * E_) * 0.01f;
}

// ---------------- driver ----------------
extern "C" void kernel_launch(void* const* d_in, const int* in_sizes, int n_in,
                              void* d_out, int out_size) {
    (void)in_sizes; (void)n_in;
    const float* hidden   = (const float*)d_in[0];
    const float* ln1_w    = (const float*)d_in[1];
    const float* wq       = (const float*)d_in[2];
    const float* wk       = (const float*)d_in[3];
    const float* wv       = (const float*)d_in[4];
    const float* wo       = (const float*)d_in[5];
    const float* ln2_w    = (const float*)d_in[6];
    const float* router_w = (const float*)d_in[7];
    const float* router_b = (const float*)d_in[8];
    const float* gate_w   = (const float*)d_in[9];
    const float* up_w     = (const float*)d_in[10];
    const float* down_w   = (const float*)d_in[11];
    float* out = (float*)d_out;

    float *sc, *h1, *x2, *rw, *red, *dp;
    __half *probs, *xnh, *xnl, *x2h, *qkh, *qkl, *vh, *vth, *oh, *gbh, *ubh;
    __half *wqkTh, *wqkTl, *wvT, *woT, *gT, *uT, *dT;
    cudaGetSymbolAddress((void**)&sc,  g_scores);
    cudaGetSymbolAddress((void**)&h1,  g_h1);
    cudaGetSymbolAddress((void**)&x2,  g_x2);
    cudaGetSymbolAddress((void**)&rw,  g_rw);
    cudaGetSymbolAddress((void**)&red, g_red);
    cudaGetSymbolAddress((void**)&dp,  g_dpart);
    cudaGetSymbolAddress((void**)&probs, g_probs);
    cudaGetSymbolAddress((void**)&xnh, g_xnh);
    cudaGetSymbolAddress((void**)&xnl, g_xnl);
    cudaGetSymbolAddress((void**)&x2h, g_x2h);
    cudaGetSymbolAddress((void**)&qkh, g_qkh);
    cudaGetSymbolAddress((void**)&qkl, g_qkl);
    cudaGetSymbolAddress((void**)&vh,  g_vh);
    cudaGetSymbolAddress((void**)&vth, g_vth);
    cudaGetSymbolAddress((void**)&oh,  g_oh);
    cudaGetSymbolAddress((void**)&gbh, g_gbh);
    cudaGetSymbolAddress((void**)&ubh, g_ubh);
    cudaGetSymbolAddress((void**)&wqkTh, g_wqkTh);
    cudaGetSymbolAddress((void**)&wqkTl, g_wqkTl);
    cudaGetSymbolAddress((void**)&wvT, g_wvT);
    cudaGetSymbolAddress((void**)&woT, g_woT);
    cudaGetSymbolAddress((void**)&gT,  g_gT);
    cudaGetSymbolAddress((void**)&uT,  g_uT);
    cudaGetSymbolAddress((void**)&dT,  g_dT);

    cudaFuncSetAttribute(hgemm<0, true>,  cudaFuncAttributeMaxDynamicSharedMemorySize, SMEM_SP);
    cudaFuncSetAttribute(hgemm<1, true>,  cudaFuncAttributeMaxDynamicSharedMemorySize, SMEM_SP);
    cudaFuncSetAttribute(hgemm<2, false>, cudaFuncAttributeMaxDynamicSharedMemorySize, SMEM_NS);
    cudaFuncSetAttribute(hgemm<3, false>, cudaFuncAttributeMaxDynamicSharedMemorySize, SMEM_NS);
    cudaFuncSetAttribute(hgemm<4, false>, cudaFuncAttributeMaxDynamicSharedMemorySize, SMEM_NS);
    cudaFuncSetAttribute(hgemm<7, false>, cudaFuncAttributeMaxDynamicSharedMemorySize, SMEM_NS);
    cudaFuncSetAttribute(hgemm<8, false>, cudaFuncAttributeMaxDynamicSharedMemorySize, SMEM_NS);

    dim3 tb(32, 8);
    // weight converts/transposes (wq -> slice 0, wk -> slice 1 of combined buffer)
    trw_kernel<true><<<dim3(32, 32, 1), tb>>>(wqkTh, wqkTl, wq, HID_, HID_);
    trw_kernel<true><<<dim3(32, 32, 1), tb>>>(wqkTh + (size_t)HID_ * HID_,
                                              wqkTl + (size_t)HID_ * HID_, wk, HID_, HID_);
    trw_kernel<false><<<dim3(32, 32, 1), tb>>>(wvT, nullptr, wv, HID_, HID_);
    trw_kernel<false><<<dim3(32, 32, 1), tb>>>(woT, nullptr, wo, HID_, HID_);
    trw_kernel<false><<<dim3(64, 32, 4), tb>>>(gT, nullptr, gate_w, HID_, IM_);
    trw_kernel<false><<<dim3(64, 32, 4), tb>>>(uT, nullptr, up_w, HID_, IM_);
    trw_kernel<false><<<dim3(32, 64, 4), tb>>>(dT, nullptr, down_w, IM_, HID_);

    // 1) rmsnorm1 -> half hi/lo
    rmsnorm_kernel<<<T_, 256>>>(hidden, ln1_w, nullptr, xnh, xnl);

    dim3 gproj(HID_ / 128, T_ / 128, 1);
    // 2) Q+K projection in ONE batched split launch (z: 0=Q, 1=K); V non-split
    dim3 gqk(HID_ / 128, T_ / 128, 2);
    hgemm<1, true><<<gqk, 256, SMEM_SP>>>(T_, HID_, HID_,
                                          xnh, xnl, HID_, 0, 0,
                                          wqkTh, wqkTl, HID_, 0, (long)HID_ * HID_,
                                          qkh, HID_, 0, (long)T_ * HID_,
                                          qkl, nullptr, 0);
    hgemm<7, false><<<gproj, 256, SMEM_NS>>>(T_, HID_, HID_, xnh, nullptr, HID_, 0, 0,
                                             wvT, nullptr, HID_, 0, 0, vh, HID_, 0, 0, nullptr, nullptr, 0);
    // v transpose per head
    trv_kernel<<<dim3(D_ / 32, S_ / 32, B_ * NH_), tb>>>(vth, vh);

    // 3) scores (split, f32 out); q = qkh slice 0, k = qkh slice 1
    __half* qh = qkh;              __half* ql = qkl;
    __half* kh = qkh + (size_t)T_ * HID_;
    __half* kl = qkl + (size_t)T_ * HID_;
    dim3 gsc(S_ / 128, S_ / 128, B_ * NH_);
    hgemm<0, true><<<gsc, 256, SMEM_SP>>>(S_, S_, D_,
                                          qh, ql, HID_, (long)S_ * HID_, D_,
                                          kh, kl, HID_, (long)S_ * HID_, D_,
                                          sc, S_, (long)NH_ * S_ * S_, (long)S_ * S_,
                                          nullptr, nullptr, 0);
    // 4) softmax -> half probs
    softmax_kernel<<<B_ * NH_ * S_, 256>>>(sc, probs);

    // 5) O = probs @ vth^T -> half oh
    dim3 gpv(D_ / 128, S_ / 128, B_ * NH_);
    hgemm<7, false><<<gpv, 256, SMEM_NS>>>(S_, D_, S_,
                                           probs, nullptr, S_, (long)NH_ * S_ * S_, (long)S_ * S_,
                                           vth, nullptr, S_, (long)NH_ * D_ * S_, (long)D_ * S_,
                                           oh, HID_, (long)S_ * HID_, (long)D_,
                                           nullptr, nullptr, 0);
    // 6) h1 = hidden + oh @ woT^T
    hgemm<2, false><<<gproj, 256, SMEM_NS>>>(T_, HID_, HID_, oh, nullptr, HID_, 0, 0,
                                             woT, nullptr, HID_, 0, 0, h1, HID_, 0, 0,
                                             (void*)hidden, nullptr, 0);
    // 7) rmsnorm2 -> f32 + half
    rmsnorm_kernel<<<T_, 256>>>(h1, ln2_w, x2, x2h, nullptr);
    // 8) router
    router_kernel<<<T_, 256>>>(x2, router_w, router_b, rw);
    // 9) balance loss
    if (out_size > T_ * HID_) {
        balance1_kernel<<<S_, 32>>>(rw, red);
        balance2_kernel<<<1, 1024>>>(red, out + (size_t)T_ * HID_);
    }

    // 10) MoE — expert-batched via blockIdx.z (zh = expert)
    dim3 gmoe(IM_ / 128, T_ / 128, E_);
    dim3 gdown(HID_ / 128, T_ / 128, E_);
    hgemm<3, false><<<gmoe, 256, SMEM_NS>>>(T_, IM_, HID_,
                                            x2h, nullptr, HID_, 0, 0,
                                            gT, nullptr, HID_, 0, (long)IM_ * HID_,
                                            gbh, IM_, 0, (long)T_ * IM_,
                                            nullptr, nullptr, 0);
    hgemm<4, false><<<gmoe, 256, SMEM_NS>>>(T_, IM_, HID_,
                                            x2h, nullptr, HID_, 0, 0,
                                            uT, nullptr, HID_, 0, (long)IM_ * HID_,
                                            ubh, IM_, 0, (long)T_ * IM_,
                                            gbh, nullptr, 0);
    hgemm<8, false><<<gdown, 256, SMEM_NS>>>(T_, HID_, IM_,
                                             ubh, nullptr, IM_, 0, (long)T_ * IM_,
                                             dT, nullptr, IM_, 0, (long)HID_ * IM_,
                                             dp, HID_, 0, (long)T_ * HID_,
                                             nullptr, rw, E_);
    // reduce: out = h1 + sum_e dpart[e]
    moe_reduce_kernel<<<(T_ * HID_ / 4) / 256, 256>>>(out, h1, dp);
}

// round 14
// speedup vs baseline: 1.0440x; 1.0440x over previous
#include <cuda_runtime.h>
#include <cuda_fp16.h>
#include <math.h>
#include <stdint.h>

#define B_   4
#define S_   2048
#define HID_ 1024
#define NH_  4
#define D_   256
#define IM_  2048
#define E_   4
#define T_   (B_*S_)   // 8192 tokens

// ---------------- scratch ----------------
__device__ float g_scores[(size_t)B_*NH_*S_*S_];            // 256 MB (f32 scores)
__device__ float g_h1[(size_t)T_*HID_];
__device__ float g_x2[(size_t)T_*HID_];
__device__ float g_rw[(size_t)T_*E_];
__device__ float g_red[S_];
__device__ float g_dpart[(size_t)E_*T_*HID_];               // 128 MB per-expert down partials
// half operands
__device__ __align__(16) __half g_probs[(size_t)B_*NH_*S_*S_];  // 128 MB
__device__ __align__(16) __half g_xnh[(size_t)T_*HID_];
__device__ __align__(16) __half g_xnl[(size_t)T_*HID_];
__device__ __align__(16) __half g_x2h[(size_t)T_*HID_];
__device__ __align__(16) __half g_qkh[(size_t)2*T_*HID_];   // q | k (hi)
__device__ __align__(16) __half g_qkl[(size_t)2*T_*HID_];   // q | k (lo)
__device__ __align__(16) __half g_vh[(size_t)T_*HID_];
__device__ __align__(16) __half g_vth[(size_t)B_*NH_*D_*S_];
__device__ __align__(16) __half g_oh[(size_t)T_*HID_];
__device__ __align__(16) __half g_gbh[(size_t)E_*T_*IM_];   // 128 MB
__device__ __align__(16) __half g_ubh[(size_t)E_*T_*IM_];   // 128 MB
// transposed half weights [N,K]
__device__ __align__(16) __half g_wqkTh[(size_t)2*HID_*HID_];  // wq | wk (hi)
__device__ __align__(16) __half g_wqkTl[(size_t)2*HID_*HID_];  // wq | wk (lo)
__device__ __align__(16) __half g_wvoT[(size_t)2*HID_*HID_];   // wv | wo
__device__ __align__(16) __half g_gT[(size_t)E_*IM_*HID_];
__device__ __align__(16) __half g_uT[(size_t)E_*IM_*HID_];
__device__ __align__(16) __half g_dT[(size_t)E_*HID_*IM_];

// ---------------- helpers ----------------
__device__ __forceinline__ void cp16(void* dst, const void* src) {
    uint32_t d = (uint32_t)__cvta_generic_to_shared(dst);
    asm volatile("cp.async.cg.shared.global [%0], [%1], 16;" :: "r"(d), "l"(src));
}
#define CP_COMMIT() asm volatile("cp.async.commit_group;" ::: "memory")
template<int N> __device__ __forceinline__ void cp_wait() {
    asm volatile("cp.async.wait_group %0;" :: "n"(N) : "memory");
}
__device__ __forceinline__ void mma_f16(float* c, const unsigned* a, const unsigned* b) {
    asm volatile("mma.sync.aligned.m16n8k16.row.col.f32.f16.f16.f32 "
                 "{%0,%1,%2,%3},{%4,%5,%6,%7},{%8,%9},{%0,%1,%2,%3};"
                 : "+f"(c[0]), "+f"(c[1]), "+f"(c[2]), "+f"(c[3])
                 : "r"(a[0]), "r"(a[1]), "r"(a[2]), "r"(a[3]),
                   "r"(b[0]), "r"(b[1]));
}

__device__ __forceinline__ float blk_sum(float v) {
    __shared__ float sm[32];
    __syncthreads();
    int lane = threadIdx.x & 31, w = threadIdx.x >> 5;
    #pragma unroll
    for (int o = 16; o; o >>= 1) v += __shfl_down_sync(0xffffffffu, v, o);
    if (lane == 0) sm[w] = v;
    __syncthreads();
    int nw = blockDim.x >> 5;
    if (w == 0) {
        v = (lane < nw) ? sm[lane] : 0.f;
        #pragma unroll
        for (int o = 16; o; o >>= 1) v += __shfl_down_sync(0xffffffffu, v, o);
        if (lane == 0) sm[0] = v;
    }
    __syncthreads();
    return sm[0];
}
__device__ __forceinline__ float blk_max(float v) {
    __shared__ float sm[32];
    __syncthreads();
    int lane = threadIdx.x & 31, w = threadIdx.x >> 5;
    #pragma unroll
    for (int o = 16; o; o >>= 1) v = fmaxf(v, __shfl_down_sync(0xffffffffu, v, o));
    if (lane == 0) sm[w] = v;
    __syncthreads();
    int nw = blockDim.x >> 5;
    if (w == 0) {
        v = (lane < nw) ? sm[lane] : -INFINITY;
        #pragma unroll
        for (int o = 16; o; o >>= 1) v = fmaxf(v, __shfl_down_sync(0xffffffffu, v, o));
        if (lane == 0) sm[0] = v;
    }
    __syncthreads();
    return sm[0];
}

// ---------------- rmsnorm (f32 out optional; half hi/lo optional) ----------------
__global__ void rmsnorm_kernel(const float* __restrict__ x, const float* __restrict__ w,
                               float* __restrict__ outf,
                               __half* __restrict__ outh, __half* __restrict__ outl) {
    size_t t = blockIdx.x;
    float4 v = ((const float4*)(x + t * HID_))[threadIdx.x];
    float s = v.x*v.x + v.y*v.y + v.z*v.z + v.w*v.w;
    s = blk_sum(s);
    float r = rsqrtf(s * (1.f / HID_) + 1e-6f);
    float4 wv = ((const float4*)w)[threadIdx.x];
    float4 o;
    o.x = v.x * wv.x * r; o.y = v.y * wv.y * r;
    o.z = v.z * wv.z * r; o.w = v.w * wv.w * r;
    if (outf) ((float4*)(outf + t * HID_))[threadIdx.x] = o;
    if (outh) {
        __half2 h01 = __floats2half2_rn(o.x, o.y);
        __half2 h23 = __floats2half2_rn(o.z, o.w);
        ((__half2*)(outh + t * HID_))[2 * threadIdx.x + 0] = h01;
        ((__half2*)(outh + t * HID_))[2 * threadIdx.x + 1] = h23;
        if (outl) {
            __half2 l01 = __floats2half2_rn(o.x - __low2float(h01), o.y - __high2float(h01));
            __half2 l23 = __floats2half2_rn(o.z - __low2float(h23), o.w - __high2float(h23));
            ((__half2*)(outl + t * HID_))[2 * threadIdx.x + 0] = l01;
            ((__half2*)(outl + t * HID_))[2 * threadIdx.x + 1] = l23;
        }
    }
}

// ---------------- weight transpose f32[R,C] -> half[C,R] (hi, opt lo) ----------------
// z-batched: input z-th matrix at in + z*R*C; outputs at oh/ol + z*R*C.
template<bool SPL, bool ZPTR>
__global__ void trw_kernel(__half* __restrict__ oh, __half* __restrict__ ol,
                           const float* __restrict__ in, int R, int C,
                           const float* __restrict__ in2) {
    __shared__ float tile[32][33];
    long zo = (long)blockIdx.z * R * C;
    const float* ip = (ZPTR && blockIdx.z == 1) ? in2 : in + (ZPTR ? 0 : zo);
    oh += zo; if (SPL) ol += zo;
    int c0 = blockIdx.x * 32, r0 = blockIdx.y * 32;
    int x = threadIdx.x, y = threadIdx.y;
    #pragma unroll
    for (int i = 0; i < 32; i += 8)
        tile[y + i][x] = ip[(long)(r0 + y + i) * C + c0 + x];
    __syncthreads();
    #pragma unroll
    for (int i = 0; i < 32; i += 8) {
        float f = tile[x][y + i];
        __half h = __float2half_rn(f);
        long idx = (long)(c0 + y + i) * R + r0 + x;
        oh[idx] = h;
        if (SPL) ol[idx] = __float2half_rn(f - __half2float(h));
    }
}

// ---------------- v transpose: half vh[T,HID] per-(b,h) [S,D] -> vth[bh][D,S] ----------------
__global__ void trv_kernel(__half* __restrict__ out, const __half* __restrict__ in) {
    __shared__ __half tile[32][33];
    int z = blockIdx.z, zb = z >> 2, zh = z & 3;
    const __half* ip = in + (long)zb * S_ * HID_ + (long)zh * D_;
    __half* op = out + (long)z * D_ * S_;
    int c0 = blockIdx.x * 32, r0 = blockIdx.y * 32;
    int x = threadIdx.x, y = threadIdx.y;
    #pragma unroll
    for (int i = 0; i < 32; i += 8)
        tile[y + i][x] = ip[(long)(r0 + y + i) * HID_ + c0 + x];
    __syncthreads();
    #pragma unroll
    for (int i = 0; i < 32; i += 8)
        op[(long)(c0 + y + i) * S_ + r0 + x] = tile[x][y + i];
}

// ================= half NT GEMM with cp.async (m16n8k16), 128x128 tile =================
// C = A[M,K] * B[N,K]^T. SPLIT: A,B given as (hi,lo) pairs.
// Non-split: TBK=64, 2 stages; split: TBK=32, 2 stages. Both occupancy 2.
// EPI: 0 f32 store | 1 elu+1 -> half hi(C)+lo(aux) | 2 f32 C=v+auxf | 3 silu->half
//      4 v*auxh->half | 7 half store | 8 f32 C = v * rs[m*rsStride + zh]

template<int EPI, bool SPLIT>
__global__ __launch_bounds__(256, 2)
void hgemm(int M, int N, int K,
           const __half* __restrict__ Ahg, const __half* __restrict__ Alg, int lda, long sAb, long sAh,
           const __half* __restrict__ Bhg, const __half* __restrict__ Blg, int ldb, long sBb, long sBh,
           void* __restrict__ Cv, int ldc, long sCb, long sCh,
           void* __restrict__ aux,
           const float* __restrict__ rs, int rsStride) {
    constexpr int TBK   = SPLIT ? 32 : 64;
    constexpr int PITCH = TBK + 8;                  // 40 or 72 halves
    constexpr int SZT   = 128 * PITCH * 2;          // bytes per tile
    constexpr int NTIL  = SPLIT ? 4 : 2;
    constexpr int STAGE = NTIL * SZT;
    constexpr int SEGS  = TBK / 8;                  // 16B segs per row

    int z  = blockIdx.z;
    int zb = z >> 2, zh = z & 3;
    Ahg += (long)zb * sAb + (long)zh * sAh;
    Bhg += (long)zb * sBb + (long)zh * sBh;
    if (SPLIT) { Alg += (long)zb * sAb + (long)zh * sAh; Blg += (long)zb * sBb + (long)zh * sBh; }
    long coff = (long)zb * sCb + (long)zh * sCh;

    extern __shared__ char smem[];

    int tid  = threadIdx.x;
    int lane = tid & 31;
    int warp = tid >> 5;
    int wm = (warp >> 2) * 64;
    int wn = (warp & 3) * 32;
    int g = lane >> 2;
    int t = lane & 3;

    int blockRow = blockIdx.y * 128;
    int blockCol = blockIdx.x * 128;
    const __half* Ab = Ahg + (long)blockRow * lda;
    const __half* Bb = Bhg + (long)blockCol * ldb;
    const __half* Alb = SPLIT ? Alg + (long)blockRow * lda : nullptr;
    const __half* Blb = SPLIT ? Blg + (long)blockCol * ldb : nullptr;

    int nIter = K / TBK;

    auto issue = [&](int st, int kt) {
        if (kt < nIter) {
            long k0 = (long)kt * TBK;
            char* sb = smem + st * STAGE;
            __half* As = (__half*)sb;
            __half* Bs = (__half*)(sb + SZT);
            #pragma unroll
            for (int c = 0; c < SEGS / 2; c++) {
                int idx = tid + c * 256;
                int row = idx / SEGS;
                int seg = (idx % SEGS) * 8;
                cp16(&As[row * PITCH + seg], Ab + (long)row * lda + k0 + seg);
                cp16(&Bs[row * PITCH + seg], Bb + (long)row * ldb + k0 + seg);
                if (SPLIT) {
                    __half* Als = (__half*)(sb + 2 * SZT);
                    __half* Bls = (__half*)(sb + 3 * SZT);
                    cp16(&Als[row * PITCH + seg], Alb + (long)row * lda + k0 + seg);
                    cp16(&Bls[row * PITCH + seg], Blb + (long)row * ldb + k0 + seg);
                }
            }
        }
        CP_COMMIT();
    };

    float acc[4][4][4] = {};

    issue(0, 0);
    issue(1, 1);
    for (int kt = 0; kt < nIter; kt++) {
        int st = kt & 1;
        cp_wait<1>();
        __syncthreads();
        char* sb = smem + st * STAGE;
        const __half* As = (const __half*)sb;
        const __half* Bs = (const __half*)(sb + SZT);
        const __half* Als = (const __half*)(sb + 2 * SZT);
        const __half* Bls = (const __half*)(sb + 3 * SZT);

        #pragma unroll
        for (int ks = 0; ks < TBK; ks += 16) {
            unsigned a[4][4], b[4][2];
            #pragma unroll
            for (int mi = 0; mi < 4; mi++) {
                const __half* base = As + (wm + mi * 16 + g) * PITCH + ks + 2 * t;
                a[mi][0] = *(const unsigned*)(base);
                a[mi][1] = *(const unsigned*)(base + 8 * PITCH);
                a[mi][2] = *(const unsigned*)(base + 8);
                a[mi][3] = *(const unsigned*)(base + 8 * PITCH + 8);
            }
            #pragma unroll
            for (int ni = 0; ni < 4; ni++) {
                const __half* base = Bs + (wn + ni * 8 + g) * PITCH + ks + 2 * t;
                b[ni][0] = *(const unsigned*)(base);
                b[ni][1] = *(const unsigned*)(base + 8);
            }
            if (!SPLIT) {
                #pragma unroll
                for (int mi = 0; mi < 4; mi++)
                    #pragma unroll
                    for (int ni = 0; ni < 4; ni++)
                        mma_f16(acc[mi][ni], a[mi], b[ni]);
            } else {
                unsigned al[4][4], bl[4][2];
                #pragma unroll
                for (int mi = 0; mi < 4; mi++) {
                    const __half* base = Als + (wm + mi * 16 + g) * PITCH + ks + 2 * t;
                    al[mi][0] = *(const unsigned*)(base);
                    al[mi][1] = *(const unsigned*)(base + 8 * PITCH);
                    al[mi][2] = *(const unsigned*)(base + 8);
                    al[mi][3] = *(const unsigned*)(base + 8 * PITCH + 8);
                }
                #pragma unroll
                for (int ni = 0; ni < 4; ni++) {
                    const __half* base = Bls + (wn + ni * 8 + g) * PITCH + ks + 2 * t;
                    bl[ni][0] = *(const unsigned*)(base);
                    bl[ni][1] = *(const unsigned*)(base + 8);
                }
                #pragma unroll
                for (int mi = 0; mi < 4; mi++)
                    #pragma unroll
                    for (int ni = 0; ni < 4; ni++) {
                        mma_f16(acc[mi][ni], a[mi], bl[ni]);
                        mma_f16(acc[mi][ni], al[mi], b[ni]);
                        mma_f16(acc[mi][ni], a[mi], b[ni]);
                    }
            }
        }
        __syncthreads();
        issue(st, kt + 2);
    }

    // ---- epilogue ----
    float* Cf = (float*)Cv + coff;
    __half* Ch = (__half*)Cv + coff;
    const float* auxf = (const float*)aux ? (const float*)aux + coff : nullptr;
    const __half* auxh = (const __half*)aux ? (const __half*)aux + coff : nullptr;
    __half* aux2h = (__half*)aux ? (__half*)aux + coff : nullptr;

    #pragma unroll
    for (int mi = 0; mi < 4; mi++) {
        int r0 = blockRow + wm + mi * 16 + g;
        int r1 = r0 + 8;
        float sc0 = 0.f, sc1 = 0.f;
        if (EPI == 8) {
            sc0 = rs[(long)r0 * rsStride + zh];
            sc1 = rs[(long)r1 * rsStride + zh];
        }
        #pragma unroll
        for (int ni = 0; ni < 4; ni++) {
            int col = blockCol + wn + ni * 8 + 2 * t;
            long i0 = (long)r0 * ldc + col;
            long i1 = (long)r1 * ldc + col;
            float v0 = acc[mi][ni][0], v1 = acc[mi][ni][1];
            float v2 = acc[mi][ni][2], v3 = acc[mi][ni][3];
            if (EPI == 0) {
                *(float2*)(Cf + i0) = make_float2(v0, v1);
                *(float2*)(Cf + i1) = make_float2(v2, v3);
            } else if (EPI == 1) {
                float e0 = (v0 > 0.f) ? v0 + 1.f : expf(v0);
                float e1 = (v1 > 0.f) ? v1 + 1.f : expf(v1);
                float e2 = (v2 > 0.f) ? v2 + 1.f : expf(v2);
                float e3 = (v3 > 0.f) ? v3 + 1.f : expf(v3);
                __half2 h0 = __floats2half2_rn(e0, e1);
                __half2 h1v = __floats2half2_rn(e2, e3);
                *(__half2*)(Ch + i0) = h0;
                *(__half2*)(Ch + i1) = h1v;
                *(__half2*)(aux2h + i0) = __floats2half2_rn(e0 - __low2float(h0), e1 - __high2float(h0));
                *(__half2*)(aux2h + i1) = __floats2half2_rn(e2 - __low2float(h1v), e3 - __high2float(h1v));
            } else if (EPI == 2) {
                float2 x0 = *(const float2*)(auxf + i0);
                float2 x1 = *(const float2*)(auxf + i1);
                *(float2*)(Cf + i0) = make_float2(v0 + x0.x, v1 + x0.y);
                *(float2*)(Cf + i1) = make_float2(v2 + x1.x, v3 + x1.y);
            } else if (EPI == 3) {
                *(__half2*)(Ch + i0) = __floats2half2_rn(v0 / (1.f + expf(-v0)), v1 / (1.f + expf(-v1)));
                *(__half2*)(Ch + i1) = __floats2half2_rn(v2 / (1.f + expf(-v2)), v3 / (1.f + expf(-v3)));
            } else if (EPI == 4) {
                __half2 g0 = *(const __half2*)(auxh + i0);
                __half2 g1 = *(const __half2*)(auxh + i1);
                *(__half2*)(Ch + i0) = __floats2half2_rn(v0 * __low2float(g0), v1 * __high2float(g0));
                *(__half2*)(Ch + i1) = __floats2half2_rn(v2 * __low2float(g1), v3 * __high2float(g1));
            } else if (EPI == 8) {
                *(float2*)(Cf + i0) = make_float2(v0 * sc0, v1 * sc0);
                *(float2*)(Cf + i1) = make_float2(v2 * sc1, v3 * sc1);
            } else { // 7
                *(__half2*)(Ch + i0) = __floats2half2_rn(v0, v1);
                *(__half2*)(Ch + i1) = __floats2half2_rn(v2, v3);
            }
        }
    }
}

#define SMEM_NS (2 * 2 * (128 * 72 * 2))   // 73728, occ 2
#define SMEM_SP (2 * 4 * (128 * 40 * 2))   // 81920, occ 2

// ---------------- MoE reduce: out = h1 + sum_e dpart[e] ----------------
__global__ void moe_reduce_kernel(float* __restrict__ out, const float* __restrict__ h1,
                                  const float* __restrict__ dp) {
    size_t i = (size_t)blockIdx.x * 256 + threadIdx.x;
    const size_t n = (size_t)T_ * HID_;
    float4 r = ((const float4*)h1)[i];
    #pragma unroll
    for (int e = 0; e < E_; e++) {
        float4 p = ((const float4*)(dp + e * n))[i];
        r.x += p.x; r.y += p.y; r.z += p.z; r.w += p.w;
    }
    ((float4*)out)[i] = r;
}

// ---------------- softmax: f32 scores -> half probs ----------------
__global__ void softmax_kernel(const float* __restrict__ x, __half* __restrict__ pr) {
    size_t row = blockIdx.x;
    const float4* p = (const float4*)(x + row * (size_t)S_);
    float4 a = p[threadIdx.x];
    float4 b = p[threadIdx.x + 256];
    float mx = fmaxf(fmaxf(fmaxf(a.x, a.y), fmaxf(a.z, a.w)),
                     fmaxf(fmaxf(b.x, b.y), fmaxf(b.z, b.w)));
    mx = blk_max(mx);
    a.x = expf(a.x - mx); a.y = expf(a.y - mx); a.z = expf(a.z - mx); a.w = expf(a.w - mx);
    b.x = expf(b.x - mx); b.y = expf(b.y - mx); b.z = expf(b.z - mx); b.w = expf(b.w - mx);
    float s = a.x + a.y + a.z + a.w + b.x + b.y + b.z + b.w;
    s = blk_sum(s);
    float inv = 1.f / s;
    __half2* o = (__half2*)(pr + row * (size_t)S_);
    o[2 * threadIdx.x + 0]   = __floats2half2_rn(a.x * inv, a.y * inv);
    o[2 * threadIdx.x + 1]   = __floats2half2_rn(a.z * inv, a.w * inv);
    o[2 * (threadIdx.x + 256) + 0] = __floats2half2_rn(b.x * inv, b.y * inv);
    o[2 * (threadIdx.x + 256) + 1] = __floats2half2_rn(b.z * inv, b.w * inv);
}

// ---------------- router ----------------
__global__ void router_kernel(const float* __restrict__ x2,
                              const float* __restrict__ rwW,
                              const float* __restrict__ rb,
                              float* __restrict__ rwOut) {
    size_t t = blockIdx.x;
    const float* x = x2 + t * HID_;
    float s0 = 0, s1 = 0, s2 = 0, s3 = 0;
    for (int j = threadIdx.x; j < HID_; j += 256) {
        float xv = x[j];
        float4 w = ((const float4*)rwW)[j];
        s0 = fmaf(xv, w.x, s0); s1 = fmaf(xv, w.y, s1);
        s2 = fmaf(xv, w.z, s2); s3 = fmaf(xv, w.w, s3);
    }
    __shared__ float sm[8][4];
    int lane = threadIdx.x & 31, w = threadIdx.x >> 5;
    #pragma unroll
    for (int o = 16; o; o >>= 1) {
        s0 += __shfl_down_sync(0xffffffffu, s0, o);
        s1 += __shfl_down_sync(0xffffffffu, s1, o);
        s2 += __shfl_down_sync(0xffffffffu, s2, o);
        s3 += __shfl_down_sync(0xffffffffu, s3, o);
    }
    if (lane == 0) { sm[w][0] = s0; sm[w][1] = s1; sm[w][2] = s2; sm[w][3] = s3; }
    __syncthreads();
    if (threadIdx.x == 0) {
        float l[4];
        #pragma unroll
        for (int e = 0; e < 4; e++) {
            float v = 0;
            #pragma unroll
            for (int ww = 0; ww < 8; ww++) v += sm[ww][e];
            l[e] = v + rb[e];
        }
        float mx = fmaxf(fmaxf(l[0], l[1]), fmaxf(l[2], l[3]));
        float sum = 0;
        #pragma unroll
        for (int e = 0; e < 4; e++) { l[e] = expf(l[e] - mx); sum += l[e]; }
        float inv = 1.f / sum;
        #pragma unroll
        for (int e = 0; e < 4; e++) rwOut[t * E_ + e] = l[e] * inv;
    }
}

// ---------------- balance loss ----------------
__global__ void balance1_kernel(const float* __restrict__ rw, float* __restrict__ red) {
    int s = blockIdx.x;
    if (threadIdx.x < 4) {
        int e = threadIdx.x;
        float m = 0;
        #pragma unroll
        for (int b = 0; b < B_; b++) m += rw[((size_t)(b * S_ + s)) * E_ + e];
        m = m * (1.f / B_) - (1.f / E_);
        float v = m * m;
        v += __shfl_xor_sync(0xF, v, 1);
        v += __shfl_xor_sync(0xF, v, 2);
        if (e == 0) red[s] = v;
    }
}
__global__ void balance2_kernel(const float* __restrict__ red, float* __restrict__ out) {
    float v = red[threadIdx.x] + red[threadIdx.x + 1024];
    v = blk_sum(v);
    if (threadIdx.x == 0) out[0] = v / ((float)S_ * E_) * 0.01f;
}

// ---------------- driver ----------------
extern "C" void kernel_launch(void* const* d_in, const int* in_sizes, int n_in,
                              void* d_out, int out_size) {
    (void)in_sizes; (void)n_in;
    const float* hidden   = (const float*)d_in[0];
    const float* ln1_w    = (const float*)d_in[1];
    const float* wq       = (const float*)d_in[2];
    const float* wk       = (const float*)d_in[3];
    const float* wv       = (const float*)d_in[4];
    const float* wo       = (const float*)d_in[5];
    const float* ln2_w    = (const float*)d_in[6];
    const float* router_w = (const float*)d_in[7];
    const float* router_b = (const float*)d_in[8];
    const float* gate_w   = (const float*)d_in[9];
    const float* up_w     = (const float*)d_in[10];
    const float* down_w   = (const float*)d_in[11];
    float* out = (float*)d_out;

    float *sc, *h1, *x2, *rw, *red, *dp;
    __half *probs, *xnh, *xnl, *x2h, *qkh, *qkl, *vh, *vth, *oh, *gbh, *ubh;
    __half *wqkTh, *wqkTl, *wvoT, *gT, *uT, *dT;
    cudaGetSymbolAddress((void**)&sc,  g_scores);
    cudaGetSymbolAddress((void**)&h1,  g_h1);
    cudaGetSymbolAddress((void**)&x2,  g_x2);
    cudaGetSymbolAddress((void**)&rw,  g_rw);
    cudaGetSymbolAddress((void**)&red, g_red);
    cudaGetSymbolAddress((void**)&dp,  g_dpart);
    cudaGetSymbolAddress((void**)&probs, g_probs);
    cudaGetSymbolAddress((void**)&xnh, g_xnh);
    cudaGetSymbolAddress((void**)&xnl, g_xnl);
    cudaGetSymbolAddress((void**)&x2h, g_x2h);
    cudaGetSymbolAddress((void**)&qkh, g_qkh);
    cudaGetSymbolAddress((void**)&qkl, g_qkl);
    cudaGetSymbolAddress((void**)&vh,  g_vh);
    cudaGetSymbolAddress((void**)&vth, g_vth);
    cudaGetSymbolAddress((void**)&oh,  g_oh);
    cudaGetSymbolAddress((void**)&gbh, g_gbh);
    cudaGetSymbolAddress((void**)&ubh, g_ubh);
    cudaGetSymbolAddress((void**)&wqkTh, g_wqkTh);
    cudaGetSymbolAddress((void**)&wqkTl, g_wqkTl);
    cudaGetSymbolAddress((void**)&wvoT, g_wvoT);
    cudaGetSymbolAddress((void**)&gT,  g_gT);
    cudaGetSymbolAddress((void**)&uT,  g_uT);
    cudaGetSymbolAddress((void**)&dT,  g_dT);

    cudaFuncSetAttribute(hgemm<0, true>,  cudaFuncAttributeMaxDynamicSharedMemorySize, SMEM_SP);
    cudaFuncSetAttribute(hgemm<1, true>,  cudaFuncAttributeMaxDynamicSharedMemorySize, SMEM_SP);
    cudaFuncSetAttribute(hgemm<2, false>, cudaFuncAttributeMaxDynamicSharedMemorySize, SMEM_NS);
    cudaFuncSetAttribute(hgemm<3, false>, cudaFuncAttributeMaxDynamicSharedMemorySize, SMEM_NS);
    cudaFuncSetAttribute(hgemm<4, false>, cudaFuncAttributeMaxDynamicSharedMemorySize, SMEM_NS);
    cudaFuncSetAttribute(hgemm<7, false>, cudaFuncAttributeMaxDynamicSharedMemorySize, SMEM_NS);
    cudaFuncSetAttribute(hgemm<8, false>, cudaFuncAttributeMaxDynamicSharedMemorySize, SMEM_NS);

    dim3 tb(32, 8);
    // weight converts/transposes — z-batched: qk split pair in one launch, v/o pair in one launch
    trw_kernel<true, true><<<dim3(32, 32, 2), tb>>>(wqkTh, wqkTl, wq, HID_, HID_, wk);
    trw_kernel<false, true><<<dim3(32, 32, 2), tb>>>(wvoT, nullptr, wv, HID_, HID_, wo);
    trw_kernel<false, false><<<dim3(64, 32, 4), tb>>>(gT, nullptr, gate_w, HID_, IM_, nullptr);
    trw_kernel<false, false><<<dim3(64, 32, 4), tb>>>(uT, nullptr, up_w, HID_, IM_, nullptr);
    trw_kernel<false, false><<<dim3(32, 64, 4), tb>>>(dT, nullptr, down_w, IM_, HID_, nullptr);

    // 1) rmsnorm1 -> half hi/lo
    rmsnorm_kernel<<<T_, 256>>>(hidden, ln1_w, nullptr, xnh, xnl);

    __half* wvT = wvoT;
    __half* woT = wvoT + (size_t)HID_ * HID_;

    dim3 gproj(HID_ / 128, T_ / 128, 1);
    // 2) Q+K projection in ONE batched split launch (z: 0=Q, 1=K); V non-split
    dim3 gqk(HID_ / 128, T_ / 128, 2);
    hgemm<1, true><<<gqk, 256, SMEM_SP>>>(T_, HID_, HID_,
                                          xnh, xnl, HID_, 0, 0,
                                          wqkTh, wqkTl, HID_, 0, (long)HID_ * HID_,
                                          qkh, HID_, 0, (long)T_ * HID_,
                                          qkl, nullptr, 0);
    hgemm<7, false><<<gproj, 256, SMEM_NS>>>(T_, HID_, HID_, xnh, nullptr, HID_, 0, 0,
                                             wvT, nullptr, HID_, 0, 0, vh, HID_, 0, 0, nullptr, nullptr, 0);
    // v transpose per head
    trv_kernel<<<dim3(D_ / 32, S_ / 32, B_ * NH_), tb>>>(vth, vh);

    // 3) scores (split, f32 out); q = qkh slice 0, k = qkh slice 1
    __half* qh = qkh;              __half* ql = qkl;
    __half* kh = qkh + (size_t)T_ * HID_;
    __half* kl = qkl + (size_t)T_ * HID_;
    dim3 gsc(S_ / 128, S_ / 128, B_ * NH_);
    hgemm<0, true><<<gsc, 256, SMEM_SP>>>(S_, S_, D_,
                                          qh, ql, HID_, (long)S_ * HID_, D_,
                                          kh, kl, HID_, (long)S_ * HID_, D_,
                                          sc, S_, (long)NH_ * S_ * S_, (long)S_ * S_,
                                          nullptr, nullptr, 0);
    // 4) softmax -> half probs
    softmax_kernel<<<B_ * NH_ * S_, 256>>>(sc, probs);

    // 5) O = probs @ vth^T -> half oh
    dim3 gpv(D_ / 128, S_ / 128, B_ * NH_);
    hgemm<7, false><<<gpv, 256, SMEM_NS>>>(S_, D_, S_,
                                           probs, nullptr, S_, (long)NH_ * S_ * S_, (long)S_ * S_,
                                           vth, nullptr, S_, (long)NH_ * D_ * S_, (long)D_ * S_,
                                           oh, HID_, (long)S_ * HID_, (long)D_,
                                           nullptr, nullptr, 0);
    // 6) h1 = hidden + oh @ woT^T
    hgemm<2, false><<<gproj, 256, SMEM_NS>>>(T_, HID_, HID_, oh, nullptr, HID_, 0, 0,
                                             woT, nullptr, HID_, 0, 0, h1, HID_, 0, 0,
                                             (void*)hidden, nullptr, 0);
    // 7) rmsnorm2 -> f32 + half
    rmsnorm_kernel<<<T_, 256>>>(h1, ln2_w, x2, x2h, nullptr);
    // 8) router
    router_kernel<<<T_, 256>>>(x2, router_w, router_b, rw);
    // 9) balance loss
    if (out_size > T_ * HID_) {
        balance1_kernel<<<S_, 32>>>(rw, red);
        balance2_kernel<<<1, 1024>>>(red, out + (size_t)T_ * HID_);
    }

    // 10) MoE — expert-batched via blockIdx.z (zh = expert)
    dim3 gmoe(IM_ / 128, T_ / 128, E_);
    dim3 gdown(HID_ / 128, T_ / 128, E_);
    hgemm<3, false><<<gmoe, 256, SMEM_NS>>>(T_, IM_, HID_,
                                            x2h, nullptr, HID_, 0, 0,
                                            gT, nullptr, HID_, 0, (long)IM_ * HID_,
                                            gbh, IM_, 0, (long)T_ * IM_,
                                            nullptr, nullptr, 0);
    hgemm<4, false><<<gmoe, 256, SMEM_NS>>>(T_, IM_, HID_,
                                            x2h, nullptr, HID_, 0, 0,
                                            uT, nullptr, HID_, 0, (long)IM_ * HID_,
                                            ubh, IM_, 0, (long)T_ * IM_,
                                            gbh, nullptr, 0);
    hgemm<8, false><<<gdown, 256, SMEM_NS>>>(T_, HID_, IM_,
                                             ubh, nullptr, IM_, 0, (long)T_ * IM_,
                                             dT, nullptr, IM_, 0, (long)HID_ * IM_,
                                             dp, HID_, 0, (long)T_ * HID_,
                                             nullptr, rw, E_);
    // reduce: out = h1 + sum_e dpart[e]
    moe_reduce_kernel<<<(T_ * HID_ / 4) / 256, 256>>>(out, h1, dp);
}

// round 15
// speedup vs baseline: 1.0610x; 1.0163x over previous
#include <cuda_runtime.h>
#include <cuda_fp16.h>
#include <math.h>
#include <stdint.h>

#define B_   4
#define S_   2048
#define HID_ 1024
#define NH_  4
#define D_   256
#define IM_  2048
#define E_   4
#define T_   (B_*S_)   // 8192 tokens

// ---------------- scratch ----------------
__device__ float g_scores[(size_t)B_*NH_*S_*S_];
__device__ float g_h1[(size_t)T_*HID_];
__device__ float g_x2[(size_t)T_*HID_];
__device__ float g_rw[(size_t)T_*E_];
__device__ float g_red[S_];
__device__ float g_dpart[(size_t)E_*T_*HID_];
// half operands
__device__ __align__(16) __half g_probs[(size_t)B_*NH_*S_*S_];
__device__ __align__(16) __half g_xnh[(size_t)T_*HID_];
__device__ __align__(16) __half g_xnl[(size_t)T_*HID_];
__device__ __align__(16) __half g_x2h[(size_t)T_*HID_];
__device__ __align__(16) __half g_qkh[(size_t)2*T_*HID_];
__device__ __align__(16) __half g_qkl[(size_t)2*T_*HID_];
__device__ __align__(16) __half g_vh[(size_t)T_*HID_];
__device__ __align__(16) __half g_vth[(size_t)B_*NH_*D_*S_];
__device__ __align__(16) __half g_oh[(size_t)T_*HID_];
__device__ __align__(16) __half g_ubh[(size_t)E_*T_*IM_];   // fused silu(g)*u
// transposed half weights [N,K]
__device__ __align__(16) __half g_wqkTh[(size_t)2*HID_*HID_];
__device__ __align__(16) __half g_wqkTl[(size_t)2*HID_*HID_];
__device__ __align__(16) __half g_wvoT[(size_t)2*HID_*HID_];
__device__ __align__(16) __half g_gT[(size_t)E_*IM_*HID_];
__device__ __align__(16) __half g_uT[(size_t)E_*IM_*HID_];
__device__ __align__(16) __half g_dT[(size_t)E_*HID_*IM_];

// ---------------- helpers ----------------
__device__ __forceinline__ void cp16(void* dst, const void* src) {
    uint32_t d = (uint32_t)__cvta_generic_to_shared(dst);
    asm volatile("cp.async.cg.shared.global [%0], [%1], 16;" :: "r"(d), "l"(src));
}
#define CP_COMMIT() asm volatile("cp.async.commit_group;" ::: "memory")
template<int N> __device__ __forceinline__ void cp_wait() {
    asm volatile("cp.async.wait_group %0;" :: "n"(N) : "memory");
}
__device__ __forceinline__ void mma_f16(float* c, const unsigned* a, const unsigned* b) {
    asm volatile("mma.sync.aligned.m16n8k16.row.col.f32.f16.f16.f32 "
                 "{%0,%1,%2,%3},{%4,%5,%6,%7},{%8,%9},{%0,%1,%2,%3};"
                 : "+f"(c[0]), "+f"(c[1]), "+f"(c[2]), "+f"(c[3])
                 : "r"(a[0]), "r"(a[1]), "r"(a[2]), "r"(a[3]),
                   "r"(b[0]), "r"(b[1]));
}

__device__ __forceinline__ float blk_sum(float v) {
    __shared__ float sm[32];
    __syncthreads();
    int lane = threadIdx.x & 31, w = threadIdx.x >> 5;
    #pragma unroll
    for (int o = 16; o; o >>= 1) v += __shfl_down_sync(0xffffffffu, v, o);
    if (lane == 0) sm[w] = v;
    __syncthreads();
    int nw = blockDim.x >> 5;
    if (w == 0) {
        v = (lane < nw) ? sm[lane] : 0.f;
        #pragma unroll
        for (int o = 16; o; o >>= 1) v += __shfl_down_sync(0xffffffffu, v, o);
        if (lane == 0) sm[0] = v;
    }
    __syncthreads();
    return sm[0];
}
__device__ __forceinline__ float blk_max(float v) {
    __shared__ float sm[32];
    __syncthreads();
    int lane = threadIdx.x & 31, w = threadIdx.x >> 5;
    #pragma unroll
    for (int o = 16; o; o >>= 1) v = fmaxf(v, __shfl_down_sync(0xffffffffu, v, o));
    if (lane == 0) sm[w] = v;
    __syncthreads();
    int nw = blockDim.x >> 5;
    if (w == 0) {
        v = (lane < nw) ? sm[lane] : -INFINITY;
        #pragma unroll
        for (int o = 16; o; o >>= 1) v = fmaxf(v, __shfl_down_sync(0xffffffffu, v, o));
        if (lane == 0) sm[0] = v;
    }
    __syncthreads();
    return sm[0];
}

// ---------------- rmsnorm ----------------
__global__ void rmsnorm_kernel(const float* __restrict__ x, const float* __restrict__ w,
                               float* __restrict__ outf,
                               __half* __restrict__ outh, __half* __restrict__ outl) {
    size_t t = blockIdx.x;
    float4 v = ((const float4*)(x + t * HID_))[threadIdx.x];
    float s = v.x*v.x + v.y*v.y + v.z*v.z + v.w*v.w;
    s = blk_sum(s);
    float r = rsqrtf(s * (1.f / HID_) + 1e-6f);
    float4 wv = ((const float4*)w)[threadIdx.x];
    float4 o;
    o.x = v.x * wv.x * r; o.y = v.y * wv.y * r;
    o.z = v.z * wv.z * r; o.w = v.w * wv.w * r;
    if (outf) ((float4*)(outf + t * HID_))[threadIdx.x] = o;
    if (outh) {
        __half2 h01 = __floats2half2_rn(o.x, o.y);
        __half2 h23 = __floats2half2_rn(o.z, o.w);
        ((__half2*)(outh + t * HID_))[2 * threadIdx.x + 0] = h01;
        ((__half2*)(outh + t * HID_))[2 * threadIdx.x + 1] = h23;
        if (outl) {
            __half2 l01 = __floats2half2_rn(o.x - __low2float(h01), o.y - __high2float(h01));
            __half2 l23 = __floats2half2_rn(o.z - __low2float(h23), o.w - __high2float(h23));
            ((__half2*)(outl + t * HID_))[2 * threadIdx.x + 0] = l01;
            ((__half2*)(outl + t * HID_))[2 * threadIdx.x + 1] = l23;
        }
    }
}

// ---------------- weight transpose f32[R,C] -> half[C,R] (hi, opt lo), z-batched ----------------
template<bool SPL, bool ZPTR>
__global__ void trw_kernel(__half* __restrict__ oh, __half* __restrict__ ol,
                           const float* __restrict__ in, int R, int C,
                           const float* __restrict__ in2) {
    __shared__ float tile[32][33];
    long zo = (long)blockIdx.z * R * C;
    const float* ip = (ZPTR && blockIdx.z == 1) ? in2 : in + (ZPTR ? 0 : zo);
    oh += zo; if (SPL) ol += zo;
    int c0 = blockIdx.x * 32, r0 = blockIdx.y * 32;
    int x = threadIdx.x, y = threadIdx.y;
    #pragma unroll
    for (int i = 0; i < 32; i += 8)
        tile[y + i][x] = ip[(long)(r0 + y + i) * C + c0 + x];
    __syncthreads();
    #pragma unroll
    for (int i = 0; i < 32; i += 8) {
        float f = tile[x][y + i];
        __half h = __float2half_rn(f);
        long idx = (long)(c0 + y + i) * R + r0 + x;
        oh[idx] = h;
        if (SPL) ol[idx] = __float2half_rn(f - __half2float(h));
    }
}

// ---------------- v transpose ----------------
__global__ void trv_kernel(__half* __restrict__ out, const __half* __restrict__ in) {
    __shared__ __half tile[32][33];
    int z = blockIdx.z, zb = z >> 2, zh = z & 3;
    const __half* ip = in + (long)zb * S_ * HID_ + (long)zh * D_;
    __half* op = out + (long)z * D_ * S_;
    int c0 = blockIdx.x * 32, r0 = blockIdx.y * 32;
    int x = threadIdx.x, y = threadIdx.y;
    #pragma unroll
    for (int i = 0; i < 32; i += 8)
        tile[y + i][x] = ip[(long)(r0 + y + i) * HID_ + c0 + x];
    __syncthreads();
    #pragma unroll
    for (int i = 0; i < 32; i += 8)
        op[(long)(c0 + y + i) * S_ + r0 + x] = tile[x][y + i];
}

// ================= half NT GEMM with cp.async (m16n8k16), 128x128 tile =================
// EPI: 0 f32 store | 1 elu+1 -> hi(C)+lo(aux) | 2 f32 C=v+auxf | 7 half store
//      8 f32 C = v * rs[m*rsStride + zh]
template<int EPI, bool SPLIT>
__global__ __launch_bounds__(256, 2)
void hgemm(int M, int N, int K,
           const __half* __restrict__ Ahg, const __half* __restrict__ Alg, int lda, long sAb, long sAh,
           const __half* __restrict__ Bhg, const __half* __restrict__ Blg, int ldb, long sBb, long sBh,
           void* __restrict__ Cv, int ldc, long sCb, long sCh,
           void* __restrict__ aux,
           const float* __restrict__ rs, int rsStride) {
    constexpr int TBK   = SPLIT ? 32 : 64;
    constexpr int PITCH = TBK + 8;
    constexpr int SZT   = 128 * PITCH * 2;
    constexpr int NTIL  = SPLIT ? 4 : 2;
    constexpr int STAGE = NTIL * SZT;
    constexpr int SEGS  = TBK / 8;

    int z  = blockIdx.z;
    int zb = z >> 2, zh = z & 3;
    Ahg += (long)zb * sAb + (long)zh * sAh;
    Bhg += (long)zb * sBb + (long)zh * sBh;
    if (SPLIT) { Alg += (long)zb * sAb + (long)zh * sAh; Blg += (long)zb * sBb + (long)zh * sBh; }
    long coff = (long)zb * sCb + (long)zh * sCh;

    extern __shared__ char smem[];

    int tid  = threadIdx.x;
    int lane = tid & 31;
    int warp = tid >> 5;
    int wm = (warp >> 2) * 64;
    int wn = (warp & 3) * 32;
    int g = lane >> 2;
    int t = lane & 3;

    int blockRow = blockIdx.y * 128;
    int blockCol = blockIdx.x * 128;
    const __half* Ab = Ahg + (long)blockRow * lda;
    const __half* Bb = Bhg + (long)blockCol * ldb;
    const __half* Alb = SPLIT ? Alg + (long)blockRow * lda : nullptr;
    const __half* Blb = SPLIT ? Blg + (long)blockCol * ldb : nullptr;

    int nIter = K / TBK;

    auto issue = [&](int st, int kt) {
        if (kt < nIter) {
            long k0 = (long)kt * TBK;
            char* sb = smem + st * STAGE;
            __half* As = (__half*)sb;
            __half* Bs = (__half*)(sb + SZT);
            #pragma unroll
            for (int c = 0; c < SEGS / 2; c++) {
                int idx = tid + c * 256;
                int row = idx / SEGS;
                int seg = (idx % SEGS) * 8;
                cp16(&As[row * PITCH + seg], Ab + (long)row * lda + k0 + seg);
                cp16(&Bs[row * PITCH + seg], Bb + (long)row * ldb + k0 + seg);
                if (SPLIT) {
                    __half* Als = (__half*)(sb + 2 * SZT);
                    __half* Bls = (__half*)(sb + 3 * SZT);
                    cp16(&Als[row * PITCH + seg], Alb + (long)row * lda + k0 + seg);
                    cp16(&Bls[row * PITCH + seg], Blb + (long)row * ldb + k0 + seg);
                }
            }
        }
        CP_COMMIT();
    };

    float acc[4][4][4] = {};

    issue(0, 0);
    issue(1, 1);
    for (int kt = 0; kt < nIter; kt++) {
        int st = kt & 1;
        cp_wait<1>();
        __syncthreads();
        char* sb = smem + st * STAGE;
        const __half* As = (const __half*)sb;
        const __half* Bs = (const __half*)(sb + SZT);
        const __half* Als = (const __half*)(sb + 2 * SZT);
        const __half* Bls = (const __half*)(sb + 3 * SZT);

        #pragma unroll
        for (int ks = 0; ks < TBK; ks += 16) {
            unsigned a[4][4], b[4][2];
            #pragma unroll
            for (int mi = 0; mi < 4; mi++) {
                const __half* base = As + (wm + mi * 16 + g) * PITCH + ks + 2 * t;
                a[mi][0] = *(const unsigned*)(base);
                a[mi][1] = *(const unsigned*)(base + 8 * PITCH);
                a[mi][2] = *(const unsigned*)(base + 8);
                a[mi][3] = *(const unsigned*)(base + 8 * PITCH + 8);
            }
            #pragma unroll
            for (int ni = 0; ni < 4; ni++) {
                const __half* base = Bs + (wn + ni * 8 + g) * PITCH + ks + 2 * t;
                b[ni][0] = *(const unsigned*)(base);
                b[ni][1] = *(const unsigned*)(base + 8);
            }
            if (!SPLIT) {
                #pragma unroll
                for (int mi = 0; mi < 4; mi++)
                    #pragma unroll
                    for (int ni = 0; ni < 4; ni++)
                        mma_f16(acc[mi][ni], a[mi], b[ni]);
            } else {
                unsigned al[4][4], bl[4][2];
                #pragma unroll
                for (int mi = 0; mi < 4; mi++) {
                    const __half* base = Als + (wm + mi * 16 + g) * PITCH + ks + 2 * t;
                    al[mi][0] = *(const unsigned*)(base);
                    al[mi][1] = *(const unsigned*)(base + 8 * PITCH);
                    al[mi][2] = *(const unsigned*)(base + 8);
                    al[mi][3] = *(const unsigned*)(base + 8 * PITCH + 8);
                }
                #pragma unroll
                for (int ni = 0; ni < 4; ni++) {
                    const __half* base = Bls + (wn + ni * 8 + g) * PITCH + ks + 2 * t;
                    bl[ni][0] = *(const unsigned*)(base);
                    bl[ni][1] = *(const unsigned*)(base + 8);
                }
                #pragma unroll
                for (int mi = 0; mi < 4; mi++)
                    #pragma unroll
                    for (int ni = 0; ni < 4; ni++) {
                        mma_f16(acc[mi][ni], a[mi], bl[ni]);
                        mma_f16(acc[mi][ni], al[mi], b[ni]);
                        mma_f16(acc[mi][ni], a[mi], b[ni]);
                    }
            }
        }
        __syncthreads();
        issue(st, kt + 2);
    }

    // ---- epilogue ----
    float* Cf = (float*)Cv + coff;
    __half* Ch = (__half*)Cv + coff;
    const float* auxf = (const float*)aux ? (const float*)aux + coff : nullptr;
    __half* aux2h = (__half*)aux ? (__half*)aux + coff : nullptr;

    #pragma unroll
    for (int mi = 0; mi < 4; mi++) {
        int r0 = blockRow + wm + mi * 16 + g;
        int r1 = r0 + 8;
        float sc0 = 0.f, sc1 = 0.f;
        if (EPI == 8) {
            sc0 = rs[(long)r0 * rsStride + zh];
            sc1 = rs[(long)r1 * rsStride + zh];
        }
        #pragma unroll
        for (int ni = 0; ni < 4; ni++) {
            int col = blockCol + wn + ni * 8 + 2 * t;
            long i0 = (long)r0 * ldc + col;
            long i1 = (long)r1 * ldc + col;
            float v0 = acc[mi][ni][0], v1 = acc[mi][ni][1];
            float v2 = acc[mi][ni][2], v3 = acc[mi][ni][3];
            if (EPI == 0) {
                *(float2*)(Cf + i0) = make_float2(v0, v1);
                *(float2*)(Cf + i1) = make_float2(v2, v3);
            } else if (EPI == 1) {
                float e0 = (v0 > 0.f) ? v0 + 1.f : expf(v0);
                float e1 = (v1 > 0.f) ? v1 + 1.f : expf(v1);
                float e2 = (v2 > 0.f) ? v2 + 1.f : expf(v2);
                float e3 = (v3 > 0.f) ? v3 + 1.f : expf(v3);
                __half2 h0 = __floats2half2_rn(e0, e1);
                __half2 h1v = __floats2half2_rn(e2, e3);
                *(__half2*)(Ch + i0) = h0;
                *(__half2*)(Ch + i1) = h1v;
                *(__half2*)(aux2h + i0) = __floats2half2_rn(e0 - __low2float(h0), e1 - __high2float(h0));
                *(__half2*)(aux2h + i1) = __floats2half2_rn(e2 - __low2float(h1v), e3 - __high2float(h1v));
            } else if (EPI == 2) {
                float2 x0 = *(const float2*)(auxf + i0);
                float2 x1 = *(const float2*)(auxf + i1);
                *(float2*)(Cf + i0) = make_float2(v0 + x0.x, v1 + x0.y);
                *(float2*)(Cf + i1) = make_float2(v2 + x1.x, v3 + x1.y);
            } else if (EPI == 8) {
                *(float2*)(Cf + i0) = make_float2(v0 * sc0, v1 * sc0);
                *(float2*)(Cf + i1) = make_float2(v2 * sc1, v3 * sc1);
            } else { // 7
                *(__half2*)(Ch + i0) = __floats2half2_rn(v0, v1);
                *(__half2*)(Ch + i1) = __floats2half2_rn(v2, v3);
            }
        }
    }
}

#define SMEM_NS (2 * 2 * (128 * 72 * 2))   // 73728, occ 2
#define SMEM_SP (2 * 4 * (128 * 40 * 2))   // 81920, occ 2

// ================= fused MoE gate+up GEMM =================
// Per CTA: A tile 128xK, gate-B and up-B tiles 64 rows each (N tile 64 per matrix).
// ubh[e][m][n] = silu(gate) * up, computed in fp32 and rounded once.
#define GUPITCH 72
#define GUSZA (128 * GUPITCH * 2)    // 18432
#define GUSZB (64 * GUPITCH * 2)     // 9216
#define GUSTAGE (GUSZA + 2 * GUSZB)  // 36864
#define SMEM_GU (2 * GUSTAGE)        // 73728, occ 2

__global__ __launch_bounds__(256, 2)
void hgemm_gu(const __half* __restrict__ Ahg, int lda,
              const __half* __restrict__ Gw, const __half* __restrict__ Uw,
              long sW, __half* __restrict__ Cv, long sC) {
    int zh = blockIdx.z;
    const __half* Gb = Gw + (long)zh * sW + (long)(blockIdx.x * 64) * HID_;
    const __half* Ub = Uw + (long)zh * sW + (long)(blockIdx.x * 64) * HID_;
    __half* Ch = Cv + (long)zh * sC;

    extern __shared__ char smem[];

    int tid  = threadIdx.x;
    int lane = tid & 31;
    int warp = tid >> 5;
    int wm = (warp >> 2) * 64;
    int wn = (warp & 3) * 16;
    int g = lane >> 2;
    int t = lane & 3;

    int blockRow = blockIdx.y * 128;
    int blockCol = blockIdx.x * 64;
    const __half* Ab = Ahg + (long)blockRow * lda;

    const int nIter = HID_ / 64;

    auto issue = [&](int st, int kt) {
        if (kt < nIter) {
            long k0 = (long)kt * 64;
            char* sb = smem + st * GUSTAGE;
            __half* As = (__half*)sb;
            __half* Gs = (__half*)(sb + GUSZA);
            __half* Us = (__half*)(sb + GUSZA + GUSZB);
            #pragma unroll
            for (int c = 0; c < 4; c++) {                 // A: 1024 cp16
                int idx = tid + c * 256;
                int row = idx >> 3;
                int seg = (idx & 7) * 8;
                cp16(&As[row * GUPITCH + seg], Ab + (long)row * lda + k0 + seg);
            }
            #pragma unroll
            for (int c = 0; c < 2; c++) {                 // G,U: 512 cp16 each
                int idx = tid + c * 256;
                int row = idx >> 3;
                int seg = (idx & 7) * 8;
                cp16(&Gs[row * GUPITCH + seg], Gb + (long)row * HID_ + k0 + seg);
                cp16(&Us[row * GUPITCH + seg], Ub + (long)row * HID_ + k0 + seg);
            }
        }
        CP_COMMIT();
    };

    float accg[4][2][4] = {};
    float accu[4][2][4] = {};

    issue(0, 0);
    issue(1, 1);
    for (int kt = 0; kt < nIter; kt++) {
        int st = kt & 1;
        cp_wait<1>();
        __syncthreads();
        char* sb = smem + st * GUSTAGE;
        const __half* As = (const __half*)sb;
        const __half* Gs = (const __half*)(sb + GUSZA);
        const __half* Us = (const __half*)(sb + GUSZA + GUSZB);

        #pragma unroll
        for (int ks = 0; ks < 64; ks += 16) {
            unsigned a[4][4], bg[2][2], bu[2][2];
            #pragma unroll
            for (int mi = 0; mi < 4; mi++) {
                const __half* base = As + (wm + mi * 16 + g) * GUPITCH + ks + 2 * t;
                a[mi][0] = *(const unsigned*)(base);
                a[mi][1] = *(const unsigned*)(base + 8 * GUPITCH);
                a[mi][2] = *(const unsigned*)(base + 8);
                a[mi][3] = *(const unsigned*)(base + 8 * GUPITCH + 8);
            }
            #pragma unroll
            for (int ni = 0; ni < 2; ni++) {
                const __half* bgp = Gs + (wn + ni * 8 + g) * GUPITCH + ks + 2 * t;
                bg[ni][0] = *(const unsigned*)(bgp);
                bg[ni][1] = *(const unsigned*)(bgp + 8);
                const __half* bup = Us + (wn + ni * 8 + g) * GUPITCH + ks + 2 * t;
                bu[ni][0] = *(const unsigned*)(bup);
                bu[ni][1] = *(const unsigned*)(bup + 8);
            }
            #pragma unroll
            for (int mi = 0; mi < 4; mi++)
                #pragma unroll
                for (int ni = 0; ni < 2; ni++) {
                    mma_f16(accg[mi][ni], a[mi], bg[ni]);
                    mma_f16(accu[mi][ni], a[mi], bu[ni]);
                }
        }
        __syncthreads();
        issue(st, kt + 2);
    }

    #pragma unroll
    for (int mi = 0; mi < 4; mi++) {
        int r0 = blockRow + wm + mi * 16 + g;
        int r1 = r0 + 8;
        #pragma unroll
        for (int ni = 0; ni < 2; ni++) {
            int col = blockCol + wn + ni * 8 + 2 * t;
            long i0 = (long)r0 * IM_ + col;
            long i1 = (long)r1 * IM_ + col;
            float g0 = accg[mi][ni][0], g1 = accg[mi][ni][1];
            float g2 = accg[mi][ni][2], g3 = accg[mi][ni][3];
            float u0 = accu[mi][ni][0], u1 = accu[mi][ni][1];
            float u2 = accu[mi][ni][2], u3 = accu[mi][ni][3];
            float s0 = g0 / (1.f + expf(-g0)) * u0;
            float s1 = g1 / (1.f + expf(-g1)) * u1;
            float s2 = g2 / (1.f + expf(-g2)) * u2;
            float s3 = g3 / (1.f + expf(-g3)) * u3;
            *(__half2*)(Ch + i0) = __floats2half2_rn(s0, s1);
            *(__half2*)(Ch + i1) = __floats2half2_rn(s2, s3);
        }
    }
}

// ---------------- MoE reduce ----------------
__global__ void moe_reduce_kernel(float* __restrict__ out, const float* __restrict__ h1,
                                  const float* __restrict__ dp) {
    size_t i = (size_t)blockIdx.x * 256 + threadIdx.x;
    const size_t n = (size_t)T_ * HID_;
    float4 r = ((const float4*)h1)[i];
    #pragma unroll
    for (int e = 0; e < E_; e++) {
        float4 p = ((const float4*)(dp + e * n))[i];
        r.x += p.x; r.y += p.y; r.z += p.z; r.w += p.w;
    }
    ((float4*)out)[i] = r;
}

// ---------------- softmax: f32 scores -> half probs ----------------
__global__ void softmax_kernel(const float* __restrict__ x, __half* __restrict__ pr) {
    size_t row = blockIdx.x;
    const float4* p = (const float4*)(x + row * (size_t)S_);
    float4 a = p[threadIdx.x];
    float4 b = p[threadIdx.x + 256];
    float mx = fmaxf(fmaxf(fmaxf(a.x, a.y), fmaxf(a.z, a.w)),
                     fmaxf(fmaxf(b.x, b.y), fmaxf(b.z, b.w)));
    mx = blk_max(mx);
    a.x = expf(a.x - mx); a.y = expf(a.y - mx); a.z = expf(a.z - mx); a.w = expf(a.w - mx);
    b.x = expf(b.x - mx); b.y = expf(b.y - mx); b.z = expf(b.z - mx); b.w = expf(b.w - mx);
    float s = a.x + a.y + a.z + a.w + b.x + b.y + b.z + b.w;
    s = blk_sum(s);
    float inv = 1.f / s;
    __half2* o = (__half2*)(pr + row * (size_t)S_);
    o[2 * threadIdx.x + 0]   = __floats2half2_rn(a.x * inv, a.y * inv);
    o[2 * threadIdx.x + 1]   = __floats2half2_rn(a.z * inv, a.w * inv);
    o[2 * (threadIdx.x + 256) + 0] = __floats2half2_rn(b.x * inv, b.y * inv);
    o[2 * (threadIdx.x + 256) + 1] = __floats2half2_rn(b.z * inv, b.w * inv);
}

// ---------------- router ----------------
__global__ void router_kernel(const float* __restrict__ x2,
                              const float* __restrict__ rwW,
                              const float* __restrict__ rb,
                              float* __restrict__ rwOut) {
    size_t t = blockIdx.x;
    const float* x = x2 + t * HID_;
    float s0 = 0, s1 = 0, s2 = 0, s3 = 0;
    for (int j = threadIdx.x; j < HID_; j += 256) {
        float xv = x[j];
        float4 w = ((const float4*)rwW)[j];
        s0 = fmaf(xv, w.x, s0); s1 = fmaf(xv, w.y, s1);
        s2 = fmaf(xv, w.z, s2); s3 = fmaf(xv, w.w, s3);
    }
    __shared__ float sm[8][4];
    int lane = threadIdx.x & 31, w = threadIdx.x >> 5;
    #pragma unroll
    for (int o = 16; o; o >>= 1) {
        s0 += __shfl_down_sync(0xffffffffu, s0, o);
        s1 += __shfl_down_sync(0xffffffffu, s1, o);
        s2 += __shfl_down_sync(0xffffffffu, s2, o);
        s3 += __shfl_down_sync(0xffffffffu, s3, o);
    }
    if (lane == 0) { sm[w][0] = s0; sm[w][1] = s1; sm[w][2] = s2; sm[w][3] = s3; }
    __syncthreads();
    if (threadIdx.x == 0) {
        float l[4];
        #pragma unroll
        for (int e = 0; e < 4; e++) {
            float v = 0;
            #pragma unroll
            for (int ww = 0; ww < 8; ww++) v += sm[ww][e];
            l[e] = v + rb[e];
        }
        float mx = fmaxf(fmaxf(l[0], l[1]), fmaxf(l[2], l[3]));
        float sum = 0;
        #pragma unroll
        for (int e = 0; e < 4; e++) { l[e] = expf(l[e] - mx); sum += l[e]; }
        float inv = 1.f / sum;
        #pragma unroll
        for (int e = 0; e < 4; e++) rwOut[t * E_ + e] = l[e] * inv;
    }
}

// ---------------- balance loss ----------------
__global__ void balance1_kernel(const float* __restrict__ rw, float* __restrict__ red) {
    int s = blockIdx.x;
    if (threadIdx.x < 4) {
        int e = threadIdx.x;
        float m = 0;
        #pragma unroll
        for (int b = 0; b < B_; b++) m += rw[((size_t)(b * S_ + s)) * E_ + e];
        m = m * (1.f / B_) - (1.f / E_);
        float v = m * m;
        v += __shfl_xor_sync(0xF, v, 1);
        v += __shfl_xor_sync(0xF, v, 2);
        if (e == 0) red[s] = v;
    }
}
__global__ void balance2_kernel(const float* __restrict__ red, float* __restrict__ out) {
    float v = red[threadIdx.x] + red[threadIdx.x + 1024];
    v = blk_sum(v);
    if (threadIdx.x == 0) out[0] = v / ((float)S_ * E_) * 0.01f;
}

// ---------------- driver ----------------
extern "C" void kernel_launch(void* const* d_in, const int* in_sizes, int n_in,
                              void* d_out, int out_size) {
    (void)in_sizes; (void)n_in;
    const float* hidden   = (const float*)d_in[0];
    const float* ln1_w    = (const float*)d_in[1];
    const float* wq       = (const float*)d_in[2];
    const float* wk       = (const float*)d_in[3];
    const float* wv       = (const float*)d_in[4];
    const float* wo       = (const float*)d_in[5];
    const float* ln2_w    = (const float*)d_in[6];
    const float* router_w = (const float*)d_in[7];
    const float* router_b = (const float*)d_in[8];
    const float* gate_w   = (const float*)d_in[9];
    const float* up_w     = (const float*)d_in[10];
    const float* down_w   = (const float*)d_in[11];
    float* out = (float*)d_out;

    float *sc, *h1, *x2, *rw, *red, *dp;
    __half *probs, *xnh, *xnl, *x2h, *qkh, *qkl, *vh, *vth, *oh, *ubh;
    __half *wqkTh, *wqkTl, *wvoT, *gT, *uT, *dT;
    cudaGetSymbolAddress((void**)&sc,  g_scores);
    cudaGetSymbolAddress((void**)&h1,  g_h1);
    cudaGetSymbolAddress((void**)&x2,  g_x2);
    cudaGetSymbolAddress((void**)&rw,  g_rw);
    cudaGetSymbolAddress((void**)&red, g_red);
    cudaGetSymbolAddress((void**)&dp,  g_dpart);
    cudaGetSymbolAddress((void**)&probs, g_probs);
    cudaGetSymbolAddress((void**)&xnh, g_xnh);
    cudaGetSymbolAddress((void**)&xnl, g_xnl);
    cudaGetSymbolAddress((void**)&x2h, g_x2h);
    cudaGetSymbolAddress((void**)&qkh, g_qkh);
    cudaGetSymbolAddress((void**)&qkl, g_qkl);
    cudaGetSymbolAddress((void**)&vh,  g_vh);
    cudaGetSymbolAddress((void**)&vth, g_vth);
    cudaGetSymbolAddress((void**)&oh,  g_oh);
    cudaGetSymbolAddress((void**)&ubh, g_ubh);
    cudaGetSymbolAddress((void**)&wqkTh, g_wqkTh);
    cudaGetSymbolAddress((void**)&wqkTl, g_wqkTl);
    cudaGetSymbolAddress((void**)&wvoT, g_wvoT);
    cudaGetSymbolAddress((void**)&gT,  g_gT);
    cudaGetSymbolAddress((void**)&uT,  g_uT);
    cudaGetSymbolAddress((void**)&dT,  g_dT);

    cudaFuncSetAttribute(hgemm<0, true>,  cudaFuncAttributeMaxDynamicSharedMemorySize, SMEM_SP);
    cudaFuncSetAttribute(hgemm<1, true>,  cudaFuncAttributeMaxDynamicSharedMemorySize, SMEM_SP);
    cudaFuncSetAttribute(hgemm<2, false>, cudaFuncAttributeMaxDynamicSharedMemorySize, SMEM_NS);
    cudaFuncSetAttribute(hgemm<7, false>, cudaFuncAttributeMaxDynamicSharedMemorySize, SMEM_NS);
    cudaFuncSetAttribute(hgemm<8, false>, cudaFuncAttributeMaxDynamicSharedMemorySize, SMEM_NS);
    cudaFuncSetAttribute(hgemm_gu,        cudaFuncAttributeMaxDynamicSharedMemorySize, SMEM_GU);

    dim3 tb(32, 8);
    // weight converts/transposes — z-batched
    trw_kernel<true, true><<<dim3(32, 32, 2), tb>>>(wqkTh, wqkTl, wq, HID_, HID_, wk);
    trw_kernel<false, true><<<dim3(32, 32, 2), tb>>>(wvoT, nullptr, wv, HID_, HID_, wo);
    trw_kernel<false, false><<<dim3(64, 32, 4), tb>>>(gT, nullptr, gate_w, HID_, IM_, nullptr);
    trw_kernel<false, false><<<dim3(64, 32, 4), tb>>>(uT, nullptr, up_w, HID_, IM_, nullptr);
    trw_kernel<false, false><<<dim3(32, 64, 4), tb>>>(dT, nullptr, down_w, IM_, HID_, nullptr);

    // 1) rmsnorm1 -> half hi/lo
    rmsnorm_kernel<<<T_, 256>>>(hidden, ln1_w, nullptr, xnh, xnl);

    __half* wvT = wvoT;
    __half* woT = wvoT + (size_t)HID_ * HID_;

    dim3 gproj(HID_ / 128, T_ / 128, 1);
    // 2) Q+K projection in ONE batched split launch (z: 0=Q, 1=K); V non-split
    dim3 gqk(HID_ / 128, T_ / 128, 2);
    hgemm<1, true><<<gqk, 256, SMEM_SP>>>(T_, HID_, HID_,
                                          xnh, xnl, HID_, 0, 0,
                                          wqkTh, wqkTl, HID_, 0, (long)HID_ * HID_,
                                          qkh, HID_, 0, (long)T_ * HID_,
                                          qkl, nullptr, 0);
    hgemm<7, false><<<gproj, 256, SMEM_NS>>>(T_, HID_, HID_, xnh, nullptr, HID_, 0, 0,
                                             wvT, nullptr, HID_, 0, 0, vh, HID_, 0, 0, nullptr, nullptr, 0);
    // v transpose per head
    trv_kernel<<<dim3(D_ / 32, S_ / 32, B_ * NH_), tb>>>(vth, vh);

    // 3) scores (split, f32 out)
    __half* qh = qkh;              __half* ql = qkl;
    __half* kh = qkh + (size_t)T_ * HID_;
    __half* kl = qkl + (size_t)T_ * HID_;
    dim3 gsc(S_ / 128, S_ / 128, B_ * NH_);
    hgemm<0, true><<<gsc, 256, SMEM_SP>>>(S_, S_, D_,
                                          qh, ql, HID_, (long)S_ * HID_, D_,
                                          kh, kl, HID_, (long)S_ * HID_, D_,
                                          sc, S_, (long)NH_ * S_ * S_, (long)S_ * S_,
                                          nullptr, nullptr, 0);
    // 4) softmax -> half probs
    softmax_kernel<<<B_ * NH_ * S_, 256>>>(sc, probs);

    // 5) O = probs @ vth^T -> half oh
    dim3 gpv(D_ / 128, S_ / 128, B_ * NH_);
    hgemm<7, false><<<gpv, 256, SMEM_NS>>>(S_, D_, S_,
                                           probs, nullptr, S_, (long)NH_ * S_ * S_, (long)S_ * S_,
                                           vth, nullptr, S_, (long)NH_ * D_ * S_, (long)D_ * S_,
                                           oh, HID_, (long)S_ * HID_, (long)D_,
                                           nullptr, nullptr, 0);
    // 6) h1 = hidden + oh @ woT^T
    hgemm<2, false><<<gproj, 256, SMEM_NS>>>(T_, HID_, HID_, oh, nullptr, HID_, 0, 0,
                                             woT, nullptr, HID_, 0, 0, h1, HID_, 0, 0,
                                             (void*)hidden, nullptr, 0);
    // 7) rmsnorm2 -> f32 + half
    rmsnorm_kernel<<<T_, 256>>>(h1, ln2_w, x2, x2h, nullptr);
    // 8) router
    router_kernel<<<T_, 256>>>(x2, router_w, router_b, rw);
    // 9) balance loss
    if (out_size > T_ * HID_) {
        balance1_kernel<<<S_, 32>>>(rw, red);
        balance2_kernel<<<1, 1024>>>(red, out + (size_t)T_ * HID_);
    }

    // 10) MoE — fused gate+up (one launch), then down, then reduce
    dim3 ggu(IM_ / 64, T_ / 128, E_);
    hgemm_gu<<<ggu, 256, SMEM_GU>>>(x2h, HID_, gT, uT, (long)IM_ * HID_,
                                    ubh, (long)T_ * IM_);
    dim3 gdown(HID_ / 128, T_ / 128, E_);
    hgemm<8, false><<<gdown, 256, SMEM_NS>>>(T_, HID_, IM_,
                                             ubh, nullptr, IM_, 0, (long)T_ * IM_,
                                             dT, nullptr, IM_, 0, (long)HID_ * IM_,
                                             dp, HID_, 0, (long)T_ * HID_,
                                             nullptr, rw, E_);
    // reduce: out = h1 + sum_e dpart[e]
    moe_reduce_kernel<<<(T_ * HID_ / 4) / 256, 256>>>(out, h1, dp);
}